// round 13
// baseline (speedup 1.0000x reference)
#include <cuda_runtime.h>
#include <cuda_bf16.h>
#include <cstdint>

#define BB 4
#define SS 1024
#define HH 16
#define DD 64
#define DMM 1024

static const size_t OUT_ELEMS = (size_t)BB * SS * DMM;        // 4194304
static const size_t ATT_ELEMS = (size_t)BB * HH * SS * SS;    // 67108864

#define ACT_N (4096 * 1024)
#define W_N   (1024 * 1024)

// Scratch (__device__ globals) — bf16 hi/lo pairs
__device__ __align__(16) __nv_bfloat16 g_XQh[ACT_N], g_XQl[ACT_N];
__device__ __align__(16) __nv_bfloat16 g_XKh[ACT_N], g_XKl[ACT_N];
__device__ __align__(16) __nv_bfloat16 g_XVh[ACT_N], g_XVl[ACT_N];
__device__ __align__(16) __nv_bfloat16 g_Wqh[W_N], g_Wql[W_N];
__device__ __align__(16) __nv_bfloat16 g_Wkh[W_N], g_Wkl[W_N];
__device__ __align__(16) __nv_bfloat16 g_Wvh[W_N], g_Wvl[W_N];
__device__ __align__(16) __nv_bfloat16 g_Woh[W_N], g_Wol[W_N];
__device__ __align__(16) __nv_bfloat16 g_Qh[ACT_N], g_Ql[ACT_N];   // [bh][s][d]
__device__ __align__(16) __nv_bfloat16 g_Kh[ACT_N], g_Kl[ACT_N];   // [bh][s][d]
__device__ __align__(16) __nv_bfloat16 g_Vth[ACT_N], g_Vtl[ACT_N]; // [bh][d][s]
__device__ __align__(16) __nv_bfloat16 g_Ch[ACT_N], g_Cl[ACT_N];   // ctx [b*s][dm]
__device__ float g_attn[(size_t)BB * HH * SS * SS];                 // fallback

// ---------------------------------------------------------------------------
__device__ __forceinline__ uint32_t smem_u32(const void* p) {
    uint32_t a;
    asm("{ .reg .u64 t; cvta.to.shared.u64 t, %1; cvt.u32.u64 %0, t; }" : "=r"(a) : "l"(p));
    return a;
}
__device__ __forceinline__ void ldsm4(uint32_t* r, uint32_t addr) {
    asm volatile("ldmatrix.sync.aligned.m8n8.x4.shared.b16 {%0,%1,%2,%3}, [%4];"
        : "=r"(r[0]), "=r"(r[1]), "=r"(r[2]), "=r"(r[3]) : "r"(addr));
}
__device__ __forceinline__ void mma16816(float* d, const uint32_t* a, uint32_t b0, uint32_t b1) {
    asm volatile("mma.sync.aligned.m16n8k16.row.col.f32.bf16.bf16.f32 "
        "{%0,%1,%2,%3}, {%4,%5,%6,%7}, {%8,%9}, {%0,%1,%2,%3};"
        : "+f"(d[0]), "+f"(d[1]), "+f"(d[2]), "+f"(d[3])
        : "r"(a[0]), "r"(a[1]), "r"(a[2]), "r"(a[3]), "r"(b0), "r"(b1));
}
__device__ __forceinline__ void cp16(uint32_t s, const void* g) {
    asm volatile("cp.async.cg.shared.global [%0], [%1], 16;" :: "r"(s), "l"(g));
}
#define CP_COMMIT() asm volatile("cp.async.commit_group;" ::: "memory")
#define CP_WAIT(N)  asm volatile("cp.async.wait_group %0;" :: "n"(N) : "memory")
#define STS64(addr, r0, r1) \
    asm volatile("st.shared.v2.b32 [%0], {%1,%2};" :: "r"(addr), "r"(r0), "r"(r1) : "memory")

__device__ __forceinline__ void cvt_pair(float x, float y, uint32_t& hi, uint32_t& lo) {
    __nv_bfloat16 hx = __float2bfloat16(x), hy = __float2bfloat16(y);
    float rx = x - __bfloat162float(hx), ry = y - __bfloat162float(hy);
    __nv_bfloat16 lx = __float2bfloat16(rx), ly = __float2bfloat16(ry);
    hi = ((uint32_t)__bfloat16_as_ushort(hy) << 16) | __bfloat16_as_ushort(hx);
    lo = ((uint32_t)__bfloat16_as_ushort(ly) << 16) | __bfloat16_as_ushort(lx);
}

// ---------------------------------------------------------------------------
// Split fp32 -> bf16 hi/lo for all 7 inputs.
// ---------------------------------------------------------------------------
__global__ void __launch_bounds__(256) split_all(
    const float* q, const float* k, const float* v,
    const float* wq, const float* wk, const float* wv, const float* wo)
{
    long i4 = (long)blockIdx.x * blockDim.x + threadIdx.x;   // float4 index
    const float* src; __nv_bfloat16 *dh, *dl; long rel;
    const long M1 = 1048576, Q4 = 262144;
    if (i4 < M1)            { src = q;  dh = g_XQh; dl = g_XQl; rel = i4; }
    else if (i4 < 2*M1)     { src = k;  dh = g_XKh; dl = g_XKl; rel = i4 - M1; }
    else if (i4 < 3*M1)     { src = v;  dh = g_XVh; dl = g_XVl; rel = i4 - 2*M1; }
    else if (i4 < 3*M1+Q4)  { src = wq; dh = g_Wqh; dl = g_Wql; rel = i4 - 3*M1; }
    else if (i4 < 3*M1+2*Q4){ src = wk; dh = g_Wkh; dl = g_Wkl; rel = i4 - 3*M1 - Q4; }
    else if (i4 < 3*M1+3*Q4){ src = wv; dh = g_Wvh; dl = g_Wvl; rel = i4 - 3*M1 - 2*Q4; }
    else                    { src = wo; dh = g_Woh; dl = g_Wol; rel = i4 - 3*M1 - 3*Q4; }
    float4 x = ((const float4*)src)[rel];
    uint32_t h0, l0, h1, l1;
    cvt_pair(x.x, x.y, h0, l0);
    cvt_pair(x.z, x.w, h1, l1);
    ((uint2*)dh)[rel] = make_uint2(h0, h1);
    ((uint2*)dl)[rel] = make_uint2(l0, l1);
}

// ---------------------------------------------------------------------------
// Combined Q/K/V projection GEMM (R12 proven): one launch, gridDim.z = 3.
// ---------------------------------------------------------------------------
__global__ void __launch_bounds__(512, 2) proj_qkv(
    const __nv_bfloat16* __restrict__ XQh, const __nv_bfloat16* __restrict__ XQl,
    const __nv_bfloat16* __restrict__ XKh, const __nv_bfloat16* __restrict__ XKl,
    const __nv_bfloat16* __restrict__ XVh, const __nv_bfloat16* __restrict__ XVl,
    const __nv_bfloat16* __restrict__ Wqh, const __nv_bfloat16* __restrict__ Wql,
    const __nv_bfloat16* __restrict__ Wkh, const __nv_bfloat16* __restrict__ Wkl,
    const __nv_bfloat16* __restrict__ Wvh, const __nv_bfloat16* __restrict__ Wvl,
    __nv_bfloat16* __restrict__ Qh, __nv_bfloat16* __restrict__ Ql,
    __nv_bfloat16* __restrict__ Kh, __nv_bfloat16* __restrict__ Kl,
    __nv_bfloat16* __restrict__ Vth, __nv_bfloat16* __restrict__ Vtl)
{
    extern __shared__ char smem[];
    constexpr int RB  = 80;
    constexpr int ASZ = 128 * RB;
    constexpr int BSZ = 128 * RB;
    constexpr int STG = 2 * ASZ + 2 * BSZ;

    const int z = blockIdx.z;
    const __nv_bfloat16* Ah = (z == 0) ? XQh : (z == 1) ? XKh : XVh;
    const __nv_bfloat16* Al = (z == 0) ? XQl : (z == 1) ? XKl : XVl;
    const __nv_bfloat16* Bh = (z == 0) ? Wqh : (z == 1) ? Wkh : Wvh;
    const __nv_bfloat16* Bl = (z == 0) ? Wql : (z == 1) ? Wkl : Wvl;
    __nv_bfloat16* Ch = (z == 0) ? Qh : (z == 1) ? Kh : Vth;
    __nv_bfloat16* Cl = (z == 0) ? Ql : (z == 1) ? Kl : Vtl;

    const uint32_t sb = smem_u32(smem);
    const int tid = threadIdx.x, lane = tid & 31, wid = tid >> 5;
    const int wm = (wid & 3) * 32, wn = (wid >> 2) * 32;
    const int m0 = blockIdx.y * 128, n0 = blockIdx.x * 128;

    Ah += (long)m0 * DMM;
    Al += (long)m0 * DMM;
    Bh += (long)n0 * DMM;
    Bl += (long)n0 * DMM;

    float acc[2][4][4];
#pragma unroll
    for (int mt = 0; mt < 2; ++mt)
#pragma unroll
        for (int nt = 0; nt < 4; ++nt)
#pragma unroll
            for (int j = 0; j < 4; ++j) acc[mt][nt][j] = 0.f;

    auto CPA = [&](int i, int st) {
        int r = tid >> 2, g = tid & 3;
        uint32_t d = sb + (uint32_t)st * STG + (uint32_t)r * RB + (uint32_t)g * 16;
        cp16(d, Ah + (long)r * DMM + i * 32 + g * 8);
        cp16(d + ASZ, Al + (long)r * DMM + i * 32 + g * 8);
    };
    auto CPB = [&](int i, int st) {
        int r = tid >> 2, g = tid & 3;
        uint32_t d = sb + (uint32_t)st * STG + 2 * ASZ + (uint32_t)r * RB + (uint32_t)g * 16;
        cp16(d, Bh + (long)r * DMM + i * 32 + g * 8);
        cp16(d + BSZ, Bl + (long)r * DMM + i * 32 + g * 8);
    };

    const int NC = DMM / 32;
    CPA(0, 0);
    CPB(0, 0);
    CP_COMMIT();

    const int aRowOff = (lane & 7) + ((lane >> 3) & 1) * 8;
    const uint32_t aColOff = (uint32_t)((lane >> 4) * 8);
    const int bRowOff = (lane & 7) + ((lane >> 4) & 1) * 8;
    const uint32_t bColOff = (uint32_t)(((lane >> 3) & 1) * 8);

    for (int i = 0; i < NC; ++i) {
        const int s = i & 1;
        if (i + 1 < NC) {
            CPA(i + 1, s ^ 1);
            CPB(i + 1, s ^ 1);
            CP_COMMIT();
            CP_WAIT(1);
        } else {
            CP_WAIT(0);
        }
        __syncthreads();

        const uint32_t aB = sb + (uint32_t)s * STG;
        const uint32_t bB = aB + 2 * ASZ;
#pragma unroll
        for (int ks = 0; ks < 2; ++ks) {
            uint32_t ah[2][4], al[2][4];
            const uint32_t ac = (aColOff + ks * 16) * 2;
#pragma unroll
            for (int mt = 0; mt < 2; ++mt) {
                uint32_t ad = aB + (uint32_t)(wm + mt * 16 + aRowOff) * RB + ac;
                ldsm4(ah[mt], ad);
                ldsm4(al[mt], ad + ASZ);
            }
            uint32_t bh[2][4], bl[2][4];
            const uint32_t bc = (bColOff + ks * 16) * 2;
#pragma unroll
            for (int p = 0; p < 2; ++p) {
                uint32_t bd = bB + (uint32_t)(wn + p * 16 + bRowOff) * RB + bc;
                ldsm4(bh[p], bd);
                ldsm4(bl[p], bd + BSZ);
            }
#pragma unroll
            for (int mt = 0; mt < 2; ++mt)
#pragma unroll
                for (int p = 0; p < 2; ++p) {
                    mma16816(acc[mt][2*p],   ah[mt], bh[p][0], bh[p][1]);
                    mma16816(acc[mt][2*p+1], ah[mt], bh[p][2], bh[p][3]);
                }
#pragma unroll
            for (int mt = 0; mt < 2; ++mt)
#pragma unroll
                for (int p = 0; p < 2; ++p) {
                    mma16816(acc[mt][2*p],   al[mt], bh[p][0], bh[p][1]);
                    mma16816(acc[mt][2*p+1], al[mt], bh[p][2], bh[p][3]);
                }
#pragma unroll
            for (int mt = 0; mt < 2; ++mt)
#pragma unroll
                for (int p = 0; p < 2; ++p) {
                    mma16816(acc[mt][2*p],   ah[mt], bl[p][0], bl[p][1]);
                    mma16816(acc[mt][2*p+1], ah[mt], bl[p][2], bl[p][3]);
                }
        }
        __syncthreads();
    }

    const int mode = (z == 2) ? 2 : 1;
#pragma unroll
    for (int mt = 0; mt < 2; ++mt)
#pragma unroll
        for (int nt = 0; nt < 4; ++nt) {
#pragma unroll
            for (int half = 0; half < 2; ++half) {
                int m = m0 + wm + mt * 16 + (lane >> 2) + half * 8;
                int n = n0 + wn + nt * 8 + (lane & 3) * 2;
                float x = acc[mt][nt][half * 2], y = acc[mt][nt][half * 2 + 1];
                int h = n >> 6, d = n & 63, b = m >> 10, sI = m & 1023;
                if (mode == 1) {
                    long idx = ((long)(b * HH + h) * SS + sI) * DD + d;
                    uint32_t hi, lo;
                    cvt_pair(x, y, hi, lo);
                    *(uint32_t*)(Ch + idx) = hi;
                    *(uint32_t*)(Cl + idx) = lo;
                } else {
                    long base = ((long)(b * HH + h) * DD + d) * SS + sI;
                    __nv_bfloat16 xh = __float2bfloat16(x);
                    __nv_bfloat16 xl = __float2bfloat16(x - __bfloat162float(xh));
                    __nv_bfloat16 yh = __float2bfloat16(y);
                    __nv_bfloat16 yl = __float2bfloat16(y - __bfloat162float(yh));
                    Ch[base] = xh; Cl[base] = xl;
                    Ch[base + SS] = yh; Cl[base + SS] = yl;
                }
            }
        }
}

// ---------------------------------------------------------------------------
// Out-projection GEMM (R8/R10 proven 2-stage): out = ctx @ Wo^T, fp32 C.
// ---------------------------------------------------------------------------
__global__ void __launch_bounds__(512, 2) gemm_out(
    const __nv_bfloat16* __restrict__ Ah, const __nv_bfloat16* __restrict__ Al,
    const __nv_bfloat16* __restrict__ Bh, const __nv_bfloat16* __restrict__ Bl,
    float* __restrict__ Cf)
{
    extern __shared__ char smem[];
    constexpr int RB  = 80;
    constexpr int ASZ = 128 * RB;
    constexpr int BSZ = 128 * RB;
    constexpr int STG = 2 * ASZ + 2 * BSZ;

    const uint32_t sb = smem_u32(smem);
    const int tid = threadIdx.x, lane = tid & 31, wid = tid >> 5;
    const int wm = (wid & 3) * 32, wn = (wid >> 2) * 32;
    const int m0 = blockIdx.y * 128, n0 = blockIdx.x * 128;

    Ah += (long)m0 * DMM;
    Al += (long)m0 * DMM;
    Bh += (long)n0 * DMM;
    Bl += (long)n0 * DMM;

    float acc[2][4][4];
#pragma unroll
    for (int mt = 0; mt < 2; ++mt)
#pragma unroll
        for (int nt = 0; nt < 4; ++nt)
#pragma unroll
            for (int j = 0; j < 4; ++j) acc[mt][nt][j] = 0.f;

    auto CPA = [&](int i, int st) {
        int r = tid >> 2, g = tid & 3;
        uint32_t d = sb + (uint32_t)st * STG + (uint32_t)r * RB + (uint32_t)g * 16;
        cp16(d, Ah + (long)r * DMM + i * 32 + g * 8);
        cp16(d + ASZ, Al + (long)r * DMM + i * 32 + g * 8);
    };
    auto CPB = [&](int i, int st) {
        int r = tid >> 2, g = tid & 3;
        uint32_t d = sb + (uint32_t)st * STG + 2 * ASZ + (uint32_t)r * RB + (uint32_t)g * 16;
        cp16(d, Bh + (long)r * DMM + i * 32 + g * 8);
        cp16(d + BSZ, Bl + (long)r * DMM + i * 32 + g * 8);
    };

    const int NC = DMM / 32;
    CPA(0, 0); CPB(0, 0); CP_COMMIT();

    const int aRowOff = (lane & 7) + ((lane >> 3) & 1) * 8;
    const uint32_t aColOff = (uint32_t)((lane >> 4) * 8);
    const int bRowOff = (lane & 7) + ((lane >> 4) & 1) * 8;
    const uint32_t bColOff = (uint32_t)(((lane >> 3) & 1) * 8);

    for (int i = 0; i < NC; ++i) {
        const int s = i & 1;
        if (i + 1 < NC) { CPA(i + 1, s ^ 1); CPB(i + 1, s ^ 1); CP_COMMIT(); CP_WAIT(1); }
        else            { CP_WAIT(0); }
        __syncthreads();

        const uint32_t aB = sb + (uint32_t)s * STG;
        const uint32_t bB = aB + 2 * ASZ;
#pragma unroll
        for (int ks = 0; ks < 2; ++ks) {
            uint32_t ah[2][4], al[2][4];
            const uint32_t ac = (aColOff + ks * 16) * 2;
#pragma unroll
            for (int mt = 0; mt < 2; ++mt) {
                uint32_t ad = aB + (uint32_t)(wm + mt * 16 + aRowOff) * RB + ac;
                ldsm4(ah[mt], ad);
                ldsm4(al[mt], ad + ASZ);
            }
            uint32_t bh[2][4], bl[2][4];
            const uint32_t bc = (bColOff + ks * 16) * 2;
#pragma unroll
            for (int p = 0; p < 2; ++p) {
                uint32_t bd = bB + (uint32_t)(wn + p * 16 + bRowOff) * RB + bc;
                ldsm4(bh[p], bd);
                ldsm4(bl[p], bd + BSZ);
            }
#pragma unroll
            for (int mt = 0; mt < 2; ++mt)
#pragma unroll
                for (int p = 0; p < 2; ++p) {
                    mma16816(acc[mt][2*p],   ah[mt], bh[p][0], bh[p][1]);
                    mma16816(acc[mt][2*p+1], ah[mt], bh[p][2], bh[p][3]);
                }
#pragma unroll
            for (int mt = 0; mt < 2; ++mt)
#pragma unroll
                for (int p = 0; p < 2; ++p) {
                    mma16816(acc[mt][2*p],   al[mt], bh[p][0], bh[p][1]);
                    mma16816(acc[mt][2*p+1], al[mt], bh[p][2], bh[p][3]);
                }
#pragma unroll
            for (int mt = 0; mt < 2; ++mt)
#pragma unroll
                for (int p = 0; p < 2; ++p) {
                    mma16816(acc[mt][2*p],   ah[mt], bl[p][0], bl[p][1]);
                    mma16816(acc[mt][2*p+1], ah[mt], bl[p][2], bl[p][3]);
                }
        }
        __syncthreads();
    }

#pragma unroll
    for (int mt = 0; mt < 2; ++mt)
#pragma unroll
        for (int nt = 0; nt < 4; ++nt) {
            int m = m0 + wm + mt * 16 + (lane >> 2);
            int n = n0 + wn + nt * 8 + (lane & 3) * 2;
            *(float2*)(Cf + (long)m * DMM + n) = make_float2(acc[mt][nt][0], acc[mt][nt][1]);
            *(float2*)(Cf + (long)(m + 8) * DMM + n) = make_float2(acc[mt][nt][2], acc[mt][nt][3]);
        }
}

// ---------------------------------------------------------------------------
// PV GEMM: ctx = attn @ V (A fp32 in-loader split, B = V^T pairs), 3-stage
// pipeline (R5-proven protocol, one sync/iter), 512 thr, 2 CTAs/SM.
// Emits ctx bf16 pairs [b*s][dm]. z = bh.
// ---------------------------------------------------------------------------
__global__ void __launch_bounds__(512, 2) gemm_pv(
    const float* __restrict__ Af,
    const __nv_bfloat16* __restrict__ Bh, const __nv_bfloat16* __restrict__ Bl,
    __nv_bfloat16* __restrict__ Ch, __nv_bfloat16* __restrict__ Cl)
{
    extern __shared__ char smem[];
    constexpr int RB  = 80;
    constexpr int ASZ = 128 * RB;                 // 10240
    constexpr int BSZ = 64 * RB;                  // 5120
    constexpr int STG = 2 * ASZ + 2 * BSZ;        // 30720
    constexpr int NST = 3;

    const uint32_t sb = smem_u32(smem);
    const int tid = threadIdx.x, lane = tid & 31, wid = tid >> 5;
    const int wm = (wid & 3) * 32, wn = (wid >> 2) * 16;
    const int m0 = blockIdx.y * 128;

    Af += (long)blockIdx.z * SS * SS + (long)m0 * SS;
    Bh += (long)blockIdx.z * DD * SS;
    Bl += (long)blockIdx.z * DD * SS;

    float acc[2][2][4];
#pragma unroll
    for (int mt = 0; mt < 2; ++mt)
#pragma unroll
        for (int nt = 0; nt < 2; ++nt)
#pragma unroll
            for (int j = 0; j < 4; ++j) acc[mt][nt][j] = 0.f;

    float4 ra[2];

    auto LDGA = [&](int i) {
#pragma unroll
        for (int t = 0; t < 2; ++t) {
            int c = tid + t * 512, r = c >> 3, g = c & 7;
            ra[t] = *(const float4*)(Af + (long)r * SS + i * 32 + g * 4);
        }
    };
    auto STSA = [&](int st) {
#pragma unroll
        for (int t = 0; t < 2; ++t) {
            int c = tid + t * 512, r = c >> 3, g = c & 7;
            uint32_t h0, l0, h1, l1;
            cvt_pair(ra[t].x, ra[t].y, h0, l0);
            cvt_pair(ra[t].z, ra[t].w, h1, l1);
            uint32_t d = sb + (uint32_t)st * STG + (uint32_t)r * RB + (uint32_t)g * 8;
            STS64(d, h0, h1);
            STS64(d + ASZ, l0, l1);
        }
    };
    auto CPB = [&](int i, int st) {
        if (tid < 256) {
            int r = tid >> 2, g = tid & 3;
            uint32_t d = sb + (uint32_t)st * STG + 2 * ASZ + (uint32_t)r * RB + (uint32_t)g * 16;
            cp16(d, Bh + (long)r * SS + i * 32 + g * 8);
            cp16(d + BSZ, Bl + (long)r * SS + i * 32 + g * 8);
        }
    };

    const int NC = SS / 32;   // 32

    // prologue: fill stages 0, 1
#pragma unroll
    for (int st = 0; st < NST - 1; ++st) {
        LDGA(st);
        CPB(st, st);
        CP_COMMIT();
        STSA(st);
    }

    const int aRowOff = (lane & 7) + ((lane >> 3) & 1) * 8;
    const uint32_t aColOff = (uint32_t)((lane >> 4) * 8);
    const int bRowOff = (lane & 7) + ((lane >> 4) & 1) * 8;
    const uint32_t bColOff = (uint32_t)(((lane >> 3) & 1) * 8);

    for (int i = 0; i < NC; ++i) {
        const int s = i % NST;
        if (i == NC - 1) CP_WAIT(0);
        else             CP_WAIT(1);
        __syncthreads();

        const uint32_t aB = sb + (uint32_t)s * STG;
        const uint32_t bB = aB + 2 * ASZ;
#pragma unroll
        for (int ks = 0; ks < 2; ++ks) {
            uint32_t ah[2][4], al[2][4];
            const uint32_t ac = (aColOff + ks * 16) * 2;
#pragma unroll
            for (int mt = 0; mt < 2; ++mt) {
                uint32_t ad = aB + (uint32_t)(wm + mt * 16 + aRowOff) * RB + ac;
                ldsm4(ah[mt], ad);
                ldsm4(al[mt], ad + ASZ);
            }
            uint32_t bh[4], bl[4];
            const uint32_t bc = (bColOff + ks * 16) * 2;
            uint32_t bd = bB + (uint32_t)(wn + bRowOff) * RB + bc;
            ldsm4(bh, bd);
            ldsm4(bl, bd + BSZ);
#pragma unroll
            for (int mt = 0; mt < 2; ++mt) {
                mma16816(acc[mt][0], ah[mt], bh[0], bh[1]);
                mma16816(acc[mt][1], ah[mt], bh[2], bh[3]);
            }
#pragma unroll
            for (int mt = 0; mt < 2; ++mt) {
                mma16816(acc[mt][0], al[mt], bh[0], bh[1]);
                mma16816(acc[mt][1], al[mt], bh[2], bh[3]);
            }
#pragma unroll
            for (int mt = 0; mt < 2; ++mt) {
                mma16816(acc[mt][0], ah[mt], bl[0], bl[1]);
                mma16816(acc[mt][1], ah[mt], bl[2], bl[3]);
            }
        }

        // prefetch chunk i+2 into slot (i+2)%3 (readers finished at sync_i)
        const int nf = i + NST - 1;
        if (nf < NC) {
            const int sf = nf % NST;
            LDGA(nf);
            CPB(nf, sf);
            CP_COMMIT();
            STSA(sf);
        }
    }

    // epilogue: ctx pairs [b*s][dm]
    const int z = blockIdx.z, b = z >> 4, h = z & 15;
#pragma unroll
    for (int mt = 0; mt < 2; ++mt)
#pragma unroll
        for (int nt = 0; nt < 2; ++nt) {
            int m = m0 + wm + mt * 16 + (lane >> 2);
            int n = wn + nt * 8 + (lane & 3) * 2;
            long i0 = ((long)(b * SS + m)) * DMM + h * DD + n;
            long i1 = i0 + 8L * DMM;
            uint32_t hi, lo;
            cvt_pair(acc[mt][nt][0], acc[mt][nt][1], hi, lo);
            *(uint32_t*)(Ch + i0) = hi;
            *(uint32_t*)(Cl + i0) = lo;
            cvt_pair(acc[mt][nt][2], acc[mt][nt][3], hi, lo);
            *(uint32_t*)(Ch + i1) = hi;
            *(uint32_t*)(Cl + i1) = lo;
        }
}

// ---------------------------------------------------------------------------
// Fused QK^T + softmax (R10 proven): 512 threads, 32 q-rows x 1024 keys / CTA.
// ---------------------------------------------------------------------------
__global__ void __launch_bounds__(512) qk_softmax(
    const __nv_bfloat16* __restrict__ Qh, const __nv_bfloat16* __restrict__ Ql,
    const __nv_bfloat16* __restrict__ Kh, const __nv_bfloat16* __restrict__ Kl,
    float* __restrict__ attn)
{
    extern __shared__ char smem[];
    constexpr int QRB  = 144;
    constexpr int QSZ  = 32 * QRB;
    constexpr int KSZ  = 128 * QRB;
    constexpr int KSTG = 2 * KSZ;
    constexpr int SOFF = 2 * QSZ + 2 * KSTG;
    constexpr int SROW = 1028;

    const uint32_t sb = smem_u32(smem);
    const uint32_t sQ = sb;
    const uint32_t sK = sb + 2 * QSZ;
    float* Sp = reinterpret_cast<float*>(smem + SOFF);
    float* Ip = reinterpret_cast<float*>(smem + SOFF + 32 * SROW * 4);

    const int tid = threadIdx.x, lane = tid & 31, wid = tid >> 5;
    const int q0 = blockIdx.x * 32;
    const int bh = blockIdx.y;
    const long qbase = ((long)bh * SS + q0) * DD;
    const long kbase = (long)bh * SS * DD;

    {
        int p = tid >> 8, rem = tid & 255;
        int r = rem >> 3, g = rem & 7;
        const __nv_bfloat16* src = (p ? Ql : Qh) + qbase + (long)r * DD + g * 8;
        cp16(sQ + (uint32_t)p * QSZ + (uint32_t)r * QRB + (uint32_t)g * 16, src);
    }
    auto CPK = [&](int nt, int st) {
#pragma unroll
        for (int j = 0; j < 4; ++j) {
            int idx = tid + j * 512;
            int p = idx >> 10, rem = idx & 1023;
            int r = rem >> 3, g = rem & 7;
            const __nv_bfloat16* src = (p ? Kl : Kh) + kbase + (long)(nt * 128 + r) * DD + g * 8;
            cp16(sK + (uint32_t)st * KSTG + (uint32_t)p * KSZ + (uint32_t)r * QRB + (uint32_t)g * 16, src);
        }
    };
    CPK(0, 0);
    CP_COMMIT();

    const int wm = (wid & 1) * 16, wn = (wid >> 1) * 16;
    const int aRowOff = (lane & 7) + ((lane >> 3) & 1) * 8;
    const uint32_t aColOff = (uint32_t)((lane >> 4) * 8);
    const int bRowOff = (lane & 7) + ((lane >> 4) & 1) * 8;
    const uint32_t bColOff = (uint32_t)(((lane >> 3) & 1) * 8);

    for (int nt = 0; nt < 8; ++nt) {
        const int s = nt & 1;
        if (nt + 1 < 8) { CPK(nt + 1, s ^ 1); CP_COMMIT(); CP_WAIT(1); }
        else            { CP_WAIT(0); }
        __syncthreads();

        float acc[2][4];
#pragma unroll
        for (int j = 0; j < 2; ++j)
#pragma unroll
            for (int v = 0; v < 4; ++v) acc[j][v] = 0.f;

        const uint32_t kB = sK + (uint32_t)s * KSTG;
#pragma unroll
        for (int ks = 0; ks < 4; ++ks) {
            uint32_t ah[4], al[4];
            const uint32_t ac = (aColOff + ks * 16) * 2;
            uint32_t ad = sQ + (uint32_t)(wm + aRowOff) * QRB + ac;
            ldsm4(ah, ad);
            ldsm4(al, ad + QSZ);
            uint32_t bhf[4], blf[4];
            const uint32_t bc = (bColOff + ks * 16) * 2;
            uint32_t bd = kB + (uint32_t)(wn + bRowOff) * QRB + bc;
            ldsm4(bhf, bd);
            ldsm4(blf, bd + KSZ);
            mma16816(acc[0], ah, bhf[0], bhf[1]);
            mma16816(acc[1], ah, bhf[2], bhf[3]);
            mma16816(acc[0], al, bhf[0], bhf[1]);
            mma16816(acc[1], al, bhf[2], bhf[3]);
            mma16816(acc[0], ah, blf[0], blf[1]);
            mma16816(acc[1], ah, blf[2], blf[3]);
        }

        const int m = wm + (lane >> 2);
#pragma unroll
        for (int j = 0; j < 2; ++j) {
            int c = nt * 128 + wn + j * 8 + (lane & 3) * 2;
            float2 e01 = make_float2(__expf(acc[j][0] * 0.125f), __expf(acc[j][1] * 0.125f));
            float2 e23 = make_float2(__expf(acc[j][2] * 0.125f), __expf(acc[j][3] * 0.125f));
            *(float2*)&Sp[(long)m * SROW + c]       = e01;
            *(float2*)&Sp[(long)(m + 8) * SROW + c] = e23;
        }
        __syncthreads();
    }

    {
        int r = tid >> 4, j = tid & 15;
        float sum = 0.f;
#pragma unroll
        for (int k = 0; k < 16; ++k) {
            float4 v = *(float4*)&Sp[(long)r * SROW + j * 4 + k * 64];
            sum += (v.x + v.y) + (v.z + v.w);
        }
        sum += __shfl_xor_sync(0xffffffffu, sum, 1);
        sum += __shfl_xor_sync(0xffffffffu, sum, 2);
        sum += __shfl_xor_sync(0xffffffffu, sum, 4);
        sum += __shfl_xor_sync(0xffffffffu, sum, 8);
        if (j == 0) Ip[r] = 1.0f / sum;
    }
    __syncthreads();

    {
        int r = tid >> 4, j = tid & 15;
        float inv = Ip[r];
        float* dst = attn + ((long)bh * SS + q0 + r) * SS;
#pragma unroll
        for (int k = 0; k < 16; ++k) {
            int c = j * 4 + k * 64;
            float4 v = *(float4*)&Sp[(long)r * SROW + c];
            v.x *= inv; v.y *= inv; v.z *= inv; v.w *= inv;
            *(float4*)&dst[c] = v;
        }
    }
}

// ---------------------------------------------------------------------------
extern "C" void kernel_launch(void* const* d_in, const int* in_sizes, int n_in,
                              void* d_out, int out_size)
{
    const float* query = (const float*)d_in[0];
    const float* key   = (const float*)d_in[1];
    const float* value = (const float*)d_in[2];
    const float* Wq    = (const float*)d_in[3];
    const float* Wk    = (const float*)d_in[4];
    const float* Wv    = (const float*)d_in[5];
    const float* Wo    = (const float*)d_in[6];
    float* out = (float*)d_out;

    __nv_bfloat16 *XQh, *XQl, *XKh, *XKl, *XVh, *XVl;
    __nv_bfloat16 *Wqh, *Wql, *Wkh, *Wkl, *Wvh, *Wvl, *Woh, *Wol;
    __nv_bfloat16 *Qh, *Ql, *Kh, *Kl, *Vth, *Vtl, *Chp, *Clp;
    float* Ap;
    cudaGetSymbolAddress((void**)&XQh, g_XQh); cudaGetSymbolAddress((void**)&XQl, g_XQl);
    cudaGetSymbolAddress((void**)&XKh, g_XKh); cudaGetSymbolAddress((void**)&XKl, g_XKl);
    cudaGetSymbolAddress((void**)&XVh, g_XVh); cudaGetSymbolAddress((void**)&XVl, g_XVl);
    cudaGetSymbolAddress((void**)&Wqh, g_Wqh); cudaGetSymbolAddress((void**)&Wql, g_Wql);
    cudaGetSymbolAddress((void**)&Wkh, g_Wkh); cudaGetSymbolAddress((void**)&Wkl, g_Wkl);
    cudaGetSymbolAddress((void**)&Wvh, g_Wvh); cudaGetSymbolAddress((void**)&Wvl, g_Wvl);
    cudaGetSymbolAddress((void**)&Woh, g_Woh); cudaGetSymbolAddress((void**)&Wol, g_Wol);
    cudaGetSymbolAddress((void**)&Qh, g_Qh);   cudaGetSymbolAddress((void**)&Ql, g_Ql);
    cudaGetSymbolAddress((void**)&Kh, g_Kh);   cudaGetSymbolAddress((void**)&Kl, g_Kl);
    cudaGetSymbolAddress((void**)&Vth, g_Vth); cudaGetSymbolAddress((void**)&Vtl, g_Vtl);
    cudaGetSymbolAddress((void**)&Chp, g_Ch);  cudaGetSymbolAddress((void**)&Clp, g_Cl);
    cudaGetSymbolAddress((void**)&Ap, g_attn);

    float* attn = ((size_t)out_size >= OUT_ELEMS + ATT_ELEMS) ? (out + OUT_ELEMS) : Ap;

    const int SM128 = 2 * (2 * 128 * 80 + 2 * 128 * 80);  // 81920
    const int SMPV  = 3 * (2 * 128 * 80 + 2 * 64 * 80);   // 92160
    const int SMQK  = 2 * (32 * 144) + 2 * (2 * 128 * 144) + 32 * 1028 * 4 + 128; // 214656
    cudaFuncSetAttribute(proj_qkv, cudaFuncAttributeMaxDynamicSharedMemorySize, SM128);
    cudaFuncSetAttribute(gemm_out, cudaFuncAttributeMaxDynamicSharedMemorySize, SM128);
    cudaFuncSetAttribute(gemm_pv,  cudaFuncAttributeMaxDynamicSharedMemorySize, SMPV);
    cudaFuncSetAttribute(qk_softmax, cudaFuncAttributeMaxDynamicSharedMemorySize, SMQK);

    // 1) split all inputs to bf16 hi/lo
    split_all<<<16384, 256>>>(query, key, value, Wq, Wk, Wv, Wo);

    dim3 blk(512);

    // 2) Q/K/V projections in ONE launch (gridDim.z = 3)
    proj_qkv<<<dim3(8, 32, 3), blk, SM128>>>(
        XQh, XQl, XKh, XKl, XVh, XVl,
        Wqh, Wql, Wkh, Wkl, Wvh, Wvl,
        Qh, Ql, Kh, Kl, Vth, Vtl);

    // 3) fused scores + softmax -> attn
    qk_softmax<<<dim3(32, 64), blk, SMQK>>>(Qh, Ql, Kh, Kl, attn);

    // 4) ctx = attn @ V  (3-stage pipeline)
    gemm_pv<<<dim3(1, 8, BB * HH), blk, SMPV>>>(attn, Vth, Vtl, Chp, Clp);

    // 5) out = ctx @ Wo^T
    gemm_out<<<dim3(8, 32, 1), blk, SM128>>>(Chp, Clp, Woh, Wol, out);
}

// round 14
// speedup vs baseline: 1.0169x; 1.0169x over previous
#include <cuda_runtime.h>
#include <cuda_bf16.h>
#include <cstdint>

#define BB 4
#define SS 1024
#define HH 16
#define DD 64
#define DMM 1024

static const size_t OUT_ELEMS = (size_t)BB * SS * DMM;        // 4194304
static const size_t ATT_ELEMS = (size_t)BB * HH * SS * SS;    // 67108864

#define ACT_N (4096 * 1024)
#define W_N   (1024 * 1024)

// Scratch (__device__ globals) — bf16 hi/lo pairs
__device__ __align__(16) __nv_bfloat16 g_XQh[ACT_N], g_XQl[ACT_N];
__device__ __align__(16) __nv_bfloat16 g_XKh[ACT_N], g_XKl[ACT_N];
__device__ __align__(16) __nv_bfloat16 g_XVh[ACT_N], g_XVl[ACT_N];
__device__ __align__(16) __nv_bfloat16 g_Wqh[W_N], g_Wql[W_N];
__device__ __align__(16) __nv_bfloat16 g_Wkh[W_N], g_Wkl[W_N];
__device__ __align__(16) __nv_bfloat16 g_Wvh[W_N], g_Wvl[W_N];
__device__ __align__(16) __nv_bfloat16 g_Woh[W_N], g_Wol[W_N];
__device__ __align__(16) __nv_bfloat16 g_Qh[ACT_N], g_Ql[ACT_N];   // [bh][s][d]
__device__ __align__(16) __nv_bfloat16 g_Kh[ACT_N], g_Kl[ACT_N];   // [bh][s][d]
__device__ __align__(16) __nv_bfloat16 g_Vth[ACT_N], g_Vtl[ACT_N]; // [bh][d][s]
__device__ __align__(16) __nv_bfloat16 g_Ch[ACT_N], g_Cl[ACT_N];   // ctx [b*s][dm]
__device__ float g_attn[(size_t)BB * HH * SS * SS];                 // fallback

// ---------------------------------------------------------------------------
__device__ __forceinline__ uint32_t smem_u32(const void* p) {
    uint32_t a;
    asm("{ .reg .u64 t; cvta.to.shared.u64 t, %1; cvt.u32.u64 %0, t; }" : "=r"(a) : "l"(p));
    return a;
}
__device__ __forceinline__ void ldsm4(uint32_t* r, uint32_t addr) {
    asm volatile("ldmatrix.sync.aligned.m8n8.x4.shared.b16 {%0,%1,%2,%3}, [%4];"
        : "=r"(r[0]), "=r"(r[1]), "=r"(r[2]), "=r"(r[3]) : "r"(addr));
}
__device__ __forceinline__ void mma16816(float* d, const uint32_t* a, uint32_t b0, uint32_t b1) {
    asm volatile("mma.sync.aligned.m16n8k16.row.col.f32.bf16.bf16.f32 "
        "{%0,%1,%2,%3}, {%4,%5,%6,%7}, {%8,%9}, {%0,%1,%2,%3};"
        : "+f"(d[0]), "+f"(d[1]), "+f"(d[2]), "+f"(d[3])
        : "r"(a[0]), "r"(a[1]), "r"(a[2]), "r"(a[3]), "r"(b0), "r"(b1));
}
__device__ __forceinline__ void cp16(uint32_t s, const void* g) {
    asm volatile("cp.async.cg.shared.global [%0], [%1], 16;" :: "r"(s), "l"(g));
}
#define CP_COMMIT() asm volatile("cp.async.commit_group;" ::: "memory")
#define CP_WAIT(N)  asm volatile("cp.async.wait_group %0;" :: "n"(N) : "memory")
#define STS64(addr, r0, r1) \
    asm volatile("st.shared.v2.b32 [%0], {%1,%2};" :: "r"(addr), "r"(r0), "r"(r1) : "memory")

__device__ __forceinline__ void cvt_pair(float x, float y, uint32_t& hi, uint32_t& lo) {
    __nv_bfloat16 hx = __float2bfloat16(x), hy = __float2bfloat16(y);
    float rx = x - __bfloat162float(hx), ry = y - __bfloat162float(hy);
    __nv_bfloat16 lx = __float2bfloat16(rx), ly = __float2bfloat16(ry);
    hi = ((uint32_t)__bfloat16_as_ushort(hy) << 16) | __bfloat16_as_ushort(hx);
    lo = ((uint32_t)__bfloat16_as_ushort(ly) << 16) | __bfloat16_as_ushort(lx);
}

// ---------------------------------------------------------------------------
// Split fp32 -> bf16 hi/lo for all 7 inputs.
// ---------------------------------------------------------------------------
__global__ void __launch_bounds__(256) split_all(
    const float* q, const float* k, const float* v,
    const float* wq, const float* wk, const float* wv, const float* wo)
{
    long i4 = (long)blockIdx.x * blockDim.x + threadIdx.x;   // float4 index
    const float* src; __nv_bfloat16 *dh, *dl; long rel;
    const long M1 = 1048576, Q4 = 262144;
    if (i4 < M1)            { src = q;  dh = g_XQh; dl = g_XQl; rel = i4; }
    else if (i4 < 2*M1)     { src = k;  dh = g_XKh; dl = g_XKl; rel = i4 - M1; }
    else if (i4 < 3*M1)     { src = v;  dh = g_XVh; dl = g_XVl; rel = i4 - 2*M1; }
    else if (i4 < 3*M1+Q4)  { src = wq; dh = g_Wqh; dl = g_Wql; rel = i4 - 3*M1; }
    else if (i4 < 3*M1+2*Q4){ src = wk; dh = g_Wkh; dl = g_Wkl; rel = i4 - 3*M1 - Q4; }
    else if (i4 < 3*M1+3*Q4){ src = wv; dh = g_Wvh; dl = g_Wvl; rel = i4 - 3*M1 - 2*Q4; }
    else                    { src = wo; dh = g_Woh; dl = g_Wol; rel = i4 - 3*M1 - 3*Q4; }
    float4 x = ((const float4*)src)[rel];
    uint32_t h0, l0, h1, l1;
    cvt_pair(x.x, x.y, h0, l0);
    cvt_pair(x.z, x.w, h1, l1);
    ((uint2*)dh)[rel] = make_uint2(h0, h1);
    ((uint2*)dl)[rel] = make_uint2(l0, l1);
}

// ---------------------------------------------------------------------------
// Combined Q/K/V projection GEMM (R12 proven): one launch, gridDim.z = 3.
// ---------------------------------------------------------------------------
__global__ void __launch_bounds__(512, 2) proj_qkv(
    const __nv_bfloat16* __restrict__ XQh, const __nv_bfloat16* __restrict__ XQl,
    const __nv_bfloat16* __restrict__ XKh, const __nv_bfloat16* __restrict__ XKl,
    const __nv_bfloat16* __restrict__ XVh, const __nv_bfloat16* __restrict__ XVl,
    const __nv_bfloat16* __restrict__ Wqh, const __nv_bfloat16* __restrict__ Wql,
    const __nv_bfloat16* __restrict__ Wkh, const __nv_bfloat16* __restrict__ Wkl,
    const __nv_bfloat16* __restrict__ Wvh, const __nv_bfloat16* __restrict__ Wvl,
    __nv_bfloat16* __restrict__ Qh, __nv_bfloat16* __restrict__ Ql,
    __nv_bfloat16* __restrict__ Kh, __nv_bfloat16* __restrict__ Kl,
    __nv_bfloat16* __restrict__ Vth, __nv_bfloat16* __restrict__ Vtl)
{
    extern __shared__ char smem[];
    constexpr int RB  = 80;
    constexpr int ASZ = 128 * RB;
    constexpr int BSZ = 128 * RB;
    constexpr int STG = 2 * ASZ + 2 * BSZ;

    const int z = blockIdx.z;
    const __nv_bfloat16* Ah = (z == 0) ? XQh : (z == 1) ? XKh : XVh;
    const __nv_bfloat16* Al = (z == 0) ? XQl : (z == 1) ? XKl : XVl;
    const __nv_bfloat16* Bh = (z == 0) ? Wqh : (z == 1) ? Wkh : Wvh;
    const __nv_bfloat16* Bl = (z == 0) ? Wql : (z == 1) ? Wkl : Wvl;
    __nv_bfloat16* Ch = (z == 0) ? Qh : (z == 1) ? Kh : Vth;
    __nv_bfloat16* Cl = (z == 0) ? Ql : (z == 1) ? Kl : Vtl;

    const uint32_t sb = smem_u32(smem);
    const int tid = threadIdx.x, lane = tid & 31, wid = tid >> 5;
    const int wm = (wid & 3) * 32, wn = (wid >> 2) * 32;
    const int m0 = blockIdx.y * 128, n0 = blockIdx.x * 128;

    Ah += (long)m0 * DMM;
    Al += (long)m0 * DMM;
    Bh += (long)n0 * DMM;
    Bl += (long)n0 * DMM;

    float acc[2][4][4];
#pragma unroll
    for (int mt = 0; mt < 2; ++mt)
#pragma unroll
        for (int nt = 0; nt < 4; ++nt)
#pragma unroll
            for (int j = 0; j < 4; ++j) acc[mt][nt][j] = 0.f;

    auto CPA = [&](int i, int st) {
        int r = tid >> 2, g = tid & 3;
        uint32_t d = sb + (uint32_t)st * STG + (uint32_t)r * RB + (uint32_t)g * 16;
        cp16(d, Ah + (long)r * DMM + i * 32 + g * 8);
        cp16(d + ASZ, Al + (long)r * DMM + i * 32 + g * 8);
    };
    auto CPB = [&](int i, int st) {
        int r = tid >> 2, g = tid & 3;
        uint32_t d = sb + (uint32_t)st * STG + 2 * ASZ + (uint32_t)r * RB + (uint32_t)g * 16;
        cp16(d, Bh + (long)r * DMM + i * 32 + g * 8);
        cp16(d + BSZ, Bl + (long)r * DMM + i * 32 + g * 8);
    };

    const int NC = DMM / 32;
    CPA(0, 0);
    CPB(0, 0);
    CP_COMMIT();

    const int aRowOff = (lane & 7) + ((lane >> 3) & 1) * 8;
    const uint32_t aColOff = (uint32_t)((lane >> 4) * 8);
    const int bRowOff = (lane & 7) + ((lane >> 4) & 1) * 8;
    const uint32_t bColOff = (uint32_t)(((lane >> 3) & 1) * 8);

    for (int i = 0; i < NC; ++i) {
        const int s = i & 1;
        if (i + 1 < NC) {
            CPA(i + 1, s ^ 1);
            CPB(i + 1, s ^ 1);
            CP_COMMIT();
            CP_WAIT(1);
        } else {
            CP_WAIT(0);
        }
        __syncthreads();

        const uint32_t aB = sb + (uint32_t)s * STG;
        const uint32_t bB = aB + 2 * ASZ;
#pragma unroll
        for (int ks = 0; ks < 2; ++ks) {
            uint32_t ah[2][4], al[2][4];
            const uint32_t ac = (aColOff + ks * 16) * 2;
#pragma unroll
            for (int mt = 0; mt < 2; ++mt) {
                uint32_t ad = aB + (uint32_t)(wm + mt * 16 + aRowOff) * RB + ac;
                ldsm4(ah[mt], ad);
                ldsm4(al[mt], ad + ASZ);
            }
            uint32_t bh[2][4], bl[2][4];
            const uint32_t bc = (bColOff + ks * 16) * 2;
#pragma unroll
            for (int p = 0; p < 2; ++p) {
                uint32_t bd = bB + (uint32_t)(wn + p * 16 + bRowOff) * RB + bc;
                ldsm4(bh[p], bd);
                ldsm4(bl[p], bd + BSZ);
            }
#pragma unroll
            for (int mt = 0; mt < 2; ++mt)
#pragma unroll
                for (int p = 0; p < 2; ++p) {
                    mma16816(acc[mt][2*p],   ah[mt], bh[p][0], bh[p][1]);
                    mma16816(acc[mt][2*p+1], ah[mt], bh[p][2], bh[p][3]);
                }
#pragma unroll
            for (int mt = 0; mt < 2; ++mt)
#pragma unroll
                for (int p = 0; p < 2; ++p) {
                    mma16816(acc[mt][2*p],   al[mt], bh[p][0], bh[p][1]);
                    mma16816(acc[mt][2*p+1], al[mt], bh[p][2], bh[p][3]);
                }
#pragma unroll
            for (int mt = 0; mt < 2; ++mt)
#pragma unroll
                for (int p = 0; p < 2; ++p) {
                    mma16816(acc[mt][2*p],   ah[mt], bl[p][0], bl[p][1]);
                    mma16816(acc[mt][2*p+1], ah[mt], bl[p][2], bl[p][3]);
                }
        }
        __syncthreads();
    }

    const int mode = (z == 2) ? 2 : 1;
#pragma unroll
    for (int mt = 0; mt < 2; ++mt)
#pragma unroll
        for (int nt = 0; nt < 4; ++nt) {
#pragma unroll
            for (int half = 0; half < 2; ++half) {
                int m = m0 + wm + mt * 16 + (lane >> 2) + half * 8;
                int n = n0 + wn + nt * 8 + (lane & 3) * 2;
                float x = acc[mt][nt][half * 2], y = acc[mt][nt][half * 2 + 1];
                int h = n >> 6, d = n & 63, b = m >> 10, sI = m & 1023;
                if (mode == 1) {
                    long idx = ((long)(b * HH + h) * SS + sI) * DD + d;
                    uint32_t hi, lo;
                    cvt_pair(x, y, hi, lo);
                    *(uint32_t*)(Ch + idx) = hi;
                    *(uint32_t*)(Cl + idx) = lo;
                } else {
                    long base = ((long)(b * HH + h) * DD + d) * SS + sI;
                    __nv_bfloat16 xh = __float2bfloat16(x);
                    __nv_bfloat16 xl = __float2bfloat16(x - __bfloat162float(xh));
                    __nv_bfloat16 yh = __float2bfloat16(y);
                    __nv_bfloat16 yl = __float2bfloat16(y - __bfloat162float(yh));
                    Ch[base] = xh; Cl[base] = xl;
                    Ch[base + SS] = yh; Cl[base + SS] = yl;
                }
            }
        }
}

// ---------------------------------------------------------------------------
// Split-precision bf16 HMMA GEMM (R8/R10 proven: 512 thr, 2 CTAs/SM, 2-stage).
// MODE: 0 fp32 row-major (*scale); 3 ctx pair out [b*s][dm] (z=bh, n=d)
// PAIRA=false: A fp32 split in-loader (attn read uses streaming __ldcs).
// ---------------------------------------------------------------------------
template<int NT, int MODE, bool PAIRA>
__global__ void __launch_bounds__(512, 2) gemm_pp(
    const __nv_bfloat16* __restrict__ Ah, const __nv_bfloat16* __restrict__ Al,
    const float* __restrict__ Af,
    const __nv_bfloat16* __restrict__ Bh, const __nv_bfloat16* __restrict__ Bl,
    float* __restrict__ Cf, __nv_bfloat16* __restrict__ Ch, __nv_bfloat16* __restrict__ Cl,
    int K, int lda, int ldb, int ldc,
    long sAz, long sBz, long sCz, float scale)
{
    extern __shared__ char smem[];
    constexpr int RB  = 80;
    constexpr int ASZ = 128 * RB;
    constexpr int BSZ = NT * RB;
    constexpr int STG = 2 * ASZ + 2 * BSZ;
    constexpr int NTP = (NT == 128) ? 2 : 1;
    constexpr int WNE = (NT == 128) ? 32 : 16;

    const uint32_t sb = smem_u32(smem);
    const int tid = threadIdx.x, lane = tid & 31, wid = tid >> 5;
    const int wm = (wid & 3) * 32, wn = (wid >> 2) * WNE;
    const int m0 = blockIdx.y * 128, n0 = blockIdx.x * NT;

    if (PAIRA) {
        Ah += (long)blockIdx.z * sAz + (long)m0 * lda;
        Al += (long)blockIdx.z * sAz + (long)m0 * lda;
    } else {
        Af += (long)blockIdx.z * sAz + (long)m0 * lda;
    }
    Bh += (long)blockIdx.z * sBz + (long)n0 * ldb;
    Bl += (long)blockIdx.z * sBz + (long)n0 * ldb;

    float acc[2][2 * NTP][4];
#pragma unroll
    for (int mt = 0; mt < 2; ++mt)
#pragma unroll
        for (int nt = 0; nt < 2 * NTP; ++nt)
#pragma unroll
            for (int j = 0; j < 4; ++j) acc[mt][nt][j] = 0.f;

    float4 ra[2];

    auto CPA = [&](int i, int st) {
        int r = tid >> 2, g = tid & 3;
        uint32_t d = sb + (uint32_t)st * STG + (uint32_t)r * RB + (uint32_t)g * 16;
        cp16(d, Ah + (long)r * lda + i * 32 + g * 8);
        cp16(d + ASZ, Al + (long)r * lda + i * 32 + g * 8);
    };
    auto CPB = [&](int i, int st) {
        if (NT == 128 || tid < 256) {
            int r = tid >> 2, g = tid & 3;
            uint32_t d = sb + (uint32_t)st * STG + 2 * ASZ + (uint32_t)r * RB + (uint32_t)g * 16;
            cp16(d, Bh + (long)r * ldb + i * 32 + g * 8);
            cp16(d + BSZ, Bl + (long)r * ldb + i * 32 + g * 8);
        }
    };
    auto LDGA = [&](int i) {
#pragma unroll
        for (int t = 0; t < 2; ++t) {
            int c = tid + t * 512, r = c >> 3, g = c & 7;
            ra[t] = __ldcs((const float4*)(Af + (long)r * lda + i * 32 + g * 4));
        }
    };
    auto STSA = [&](int st) {
#pragma unroll
        for (int t = 0; t < 2; ++t) {
            int c = tid + t * 512, r = c >> 3, g = c & 7;
            uint32_t h0, l0, h1, l1;
            cvt_pair(ra[t].x, ra[t].y, h0, l0);
            cvt_pair(ra[t].z, ra[t].w, h1, l1);
            uint32_t d = sb + (uint32_t)st * STG + (uint32_t)r * RB + (uint32_t)g * 8;
            STS64(d, h0, h1);
            STS64(d + ASZ, l0, l1);
        }
    };

    const int NC = K / 32;
    if (PAIRA) CPA(0, 0); else LDGA(0);
    CPB(0, 0);
    CP_COMMIT();
    if (!PAIRA) STSA(0);

    const int aRowOff = (lane & 7) + ((lane >> 3) & 1) * 8;
    const uint32_t aColOff = (uint32_t)((lane >> 4) * 8);
    const int bRowOff = (lane & 7) + ((lane >> 4) & 1) * 8;
    const uint32_t bColOff = (uint32_t)(((lane >> 3) & 1) * 8);

    for (int i = 0; i < NC; ++i) {
        const int s = i & 1;
        if (i + 1 < NC) {
            if (PAIRA) CPA(i + 1, s ^ 1);
            else       LDGA(i + 1);
            CPB(i + 1, s ^ 1);
            CP_COMMIT();
            CP_WAIT(1);
        } else {
            CP_WAIT(0);
        }
        __syncthreads();

        const uint32_t aB = sb + (uint32_t)s * STG;
        const uint32_t bB = aB + 2 * ASZ;
#pragma unroll
        for (int ks = 0; ks < 2; ++ks) {
            uint32_t ah[2][4], al[2][4];
            const uint32_t ac = (aColOff + ks * 16) * 2;
#pragma unroll
            for (int mt = 0; mt < 2; ++mt) {
                uint32_t ad = aB + (uint32_t)(wm + mt * 16 + aRowOff) * RB + ac;
                ldsm4(ah[mt], ad);
                ldsm4(al[mt], ad + ASZ);
            }
            uint32_t bh[NTP][4], bl[NTP][4];
            const uint32_t bc = (bColOff + ks * 16) * 2;
#pragma unroll
            for (int p = 0; p < NTP; ++p) {
                uint32_t bd = bB + (uint32_t)(wn + p * 16 + bRowOff) * RB + bc;
                ldsm4(bh[p], bd);
                ldsm4(bl[p], bd + BSZ);
            }
#pragma unroll
            for (int mt = 0; mt < 2; ++mt)
#pragma unroll
                for (int p = 0; p < NTP; ++p) {
                    mma16816(acc[mt][2*p],   ah[mt], bh[p][0], bh[p][1]);
                    mma16816(acc[mt][2*p+1], ah[mt], bh[p][2], bh[p][3]);
                }
#pragma unroll
            for (int mt = 0; mt < 2; ++mt)
#pragma unroll
                for (int p = 0; p < NTP; ++p) {
                    mma16816(acc[mt][2*p],   al[mt], bh[p][0], bh[p][1]);
                    mma16816(acc[mt][2*p+1], al[mt], bh[p][2], bh[p][3]);
                }
#pragma unroll
            for (int mt = 0; mt < 2; ++mt)
#pragma unroll
                for (int p = 0; p < NTP; ++p) {
                    mma16816(acc[mt][2*p],   ah[mt], bl[p][0], bl[p][1]);
                    mma16816(acc[mt][2*p+1], ah[mt], bl[p][2], bl[p][3]);
                }
        }
        if (!PAIRA && i + 1 < NC) STSA(s ^ 1);
        __syncthreads();
    }

    auto emit = [&](int m, int n, float x, float y) {
        if (MODE == 0) {
            float* p = Cf + (long)blockIdx.z * sCz + (long)m * ldc + n;
            *(float2*)p = make_float2(x * scale, y * scale);
        } else {
            int z = blockIdx.z, b = z >> 4, h = z & 15;
            long idx = ((long)(b * SS + m)) * DMM + h * DD + n;
            uint32_t hi, lo;
            cvt_pair(x, y, hi, lo);
            *(uint32_t*)(Ch + idx) = hi;
            *(uint32_t*)(Cl + idx) = lo;
        }
    };

#pragma unroll
    for (int mt = 0; mt < 2; ++mt)
#pragma unroll
        for (int nt = 0; nt < 2 * NTP; ++nt) {
            int m = m0 + wm + mt * 16 + (lane >> 2);
            int n = n0 + wn + nt * 8 + (lane & 3) * 2;
            emit(m,     n, acc[mt][nt][0], acc[mt][nt][1]);
            emit(m + 8, n, acc[mt][nt][2], acc[mt][nt][3]);
        }
}

// ---------------------------------------------------------------------------
// Fused QK^T + softmax (R10 proven): 512 threads, 32 q-rows x 1024 keys / CTA.
// attn written with streaming (__stcs) — zero L2 reuse before PV's one read.
// ---------------------------------------------------------------------------
__global__ void __launch_bounds__(512) qk_softmax(
    const __nv_bfloat16* __restrict__ Qh, const __nv_bfloat16* __restrict__ Ql,
    const __nv_bfloat16* __restrict__ Kh, const __nv_bfloat16* __restrict__ Kl,
    float* __restrict__ attn)
{
    extern __shared__ char smem[];
    constexpr int QRB  = 144;
    constexpr int QSZ  = 32 * QRB;
    constexpr int KSZ  = 128 * QRB;
    constexpr int KSTG = 2 * KSZ;
    constexpr int SOFF = 2 * QSZ + 2 * KSTG;
    constexpr int SROW = 1028;

    const uint32_t sb = smem_u32(smem);
    const uint32_t sQ = sb;
    const uint32_t sK = sb + 2 * QSZ;
    float* Sp = reinterpret_cast<float*>(smem + SOFF);
    float* Ip = reinterpret_cast<float*>(smem + SOFF + 32 * SROW * 4);

    const int tid = threadIdx.x, lane = tid & 31, wid = tid >> 5;
    const int q0 = blockIdx.x * 32;
    const int bh = blockIdx.y;
    const long qbase = ((long)bh * SS + q0) * DD;
    const long kbase = (long)bh * SS * DD;

    {
        int p = tid >> 8, rem = tid & 255;
        int r = rem >> 3, g = rem & 7;
        const __nv_bfloat16* src = (p ? Ql : Qh) + qbase + (long)r * DD + g * 8;
        cp16(sQ + (uint32_t)p * QSZ + (uint32_t)r * QRB + (uint32_t)g * 16, src);
    }
    auto CPK = [&](int nt, int st) {
#pragma unroll
        for (int j = 0; j < 4; ++j) {
            int idx = tid + j * 512;
            int p = idx >> 10, rem = idx & 1023;
            int r = rem >> 3, g = rem & 7;
            const __nv_bfloat16* src = (p ? Kl : Kh) + kbase + (long)(nt * 128 + r) * DD + g * 8;
            cp16(sK + (uint32_t)st * KSTG + (uint32_t)p * KSZ + (uint32_t)r * QRB + (uint32_t)g * 16, src);
        }
    };
    CPK(0, 0);
    CP_COMMIT();

    const int wm = (wid & 1) * 16, wn = (wid >> 1) * 16;
    const int aRowOff = (lane & 7) + ((lane >> 3) & 1) * 8;
    const uint32_t aColOff = (uint32_t)((lane >> 4) * 8);
    const int bRowOff = (lane & 7) + ((lane >> 4) & 1) * 8;
    const uint32_t bColOff = (uint32_t)(((lane >> 3) & 1) * 8);

    for (int nt = 0; nt < 8; ++nt) {
        const int s = nt & 1;
        if (nt + 1 < 8) { CPK(nt + 1, s ^ 1); CP_COMMIT(); CP_WAIT(1); }
        else            { CP_WAIT(0); }
        __syncthreads();

        float acc[2][4];
#pragma unroll
        for (int j = 0; j < 2; ++j)
#pragma unroll
            for (int v = 0; v < 4; ++v) acc[j][v] = 0.f;

        const uint32_t kB = sK + (uint32_t)s * KSTG;
#pragma unroll
        for (int ks = 0; ks < 4; ++ks) {
            uint32_t ah[4], al[4];
            const uint32_t ac = (aColOff + ks * 16) * 2;
            uint32_t ad = sQ + (uint32_t)(wm + aRowOff) * QRB + ac;
            ldsm4(ah, ad);
            ldsm4(al, ad + QSZ);
            uint32_t bhf[4], blf[4];
            const uint32_t bc = (bColOff + ks * 16) * 2;
            uint32_t bd = kB + (uint32_t)(wn + bRowOff) * QRB + bc;
            ldsm4(bhf, bd);
            ldsm4(blf, bd + KSZ);
            mma16816(acc[0], ah, bhf[0], bhf[1]);
            mma16816(acc[1], ah, bhf[2], bhf[3]);
            mma16816(acc[0], al, bhf[0], bhf[1]);
            mma16816(acc[1], al, bhf[2], bhf[3]);
            mma16816(acc[0], ah, blf[0], blf[1]);
            mma16816(acc[1], ah, blf[2], blf[3]);
        }

        const int m = wm + (lane >> 2);
#pragma unroll
        for (int j = 0; j < 2; ++j) {
            int c = nt * 128 + wn + j * 8 + (lane & 3) * 2;
            float2 e01 = make_float2(__expf(acc[j][0] * 0.125f), __expf(acc[j][1] * 0.125f));
            float2 e23 = make_float2(__expf(acc[j][2] * 0.125f), __expf(acc[j][3] * 0.125f));
            *(float2*)&Sp[(long)m * SROW + c]       = e01;
            *(float2*)&Sp[(long)(m + 8) * SROW + c] = e23;
        }
        __syncthreads();
    }

    {
        int r = tid >> 4, j = tid & 15;
        float sum = 0.f;
#pragma unroll
        for (int k = 0; k < 16; ++k) {
            float4 v = *(float4*)&Sp[(long)r * SROW + j * 4 + k * 64];
            sum += (v.x + v.y) + (v.z + v.w);
        }
        sum += __shfl_xor_sync(0xffffffffu, sum, 1);
        sum += __shfl_xor_sync(0xffffffffu, sum, 2);
        sum += __shfl_xor_sync(0xffffffffu, sum, 4);
        sum += __shfl_xor_sync(0xffffffffu, sum, 8);
        if (j == 0) Ip[r] = 1.0f / sum;
    }
    __syncthreads();

    {
        int r = tid >> 4, j = tid & 15;
        float inv = Ip[r];
        float* dst = attn + ((long)bh * SS + q0 + r) * SS;
#pragma unroll
        for (int k = 0; k < 16; ++k) {
            int c = j * 4 + k * 64;
            float4 v = *(float4*)&Sp[(long)r * SROW + c];
            v.x *= inv; v.y *= inv; v.z *= inv; v.w *= inv;
            __stcs((float4*)&dst[c], v);
        }
    }
}

// ---------------------------------------------------------------------------
extern "C" void kernel_launch(void* const* d_in, const int* in_sizes, int n_in,
                              void* d_out, int out_size)
{
    const float* query = (const float*)d_in[0];
    const float* key   = (const float*)d_in[1];
    const float* value = (const float*)d_in[2];
    const float* Wq    = (const float*)d_in[3];
    const float* Wk    = (const float*)d_in[4];
    const float* Wv    = (const float*)d_in[5];
    const float* Wo    = (const float*)d_in[6];
    float* out = (float*)d_out;

    __nv_bfloat16 *XQh, *XQl, *XKh, *XKl, *XVh, *XVl;
    __nv_bfloat16 *Wqh, *Wql, *Wkh, *Wkl, *Wvh, *Wvl, *Woh, *Wol;
    __nv_bfloat16 *Qh, *Ql, *Kh, *Kl, *Vth, *Vtl, *Chp, *Clp;
    float* Ap;
    cudaGetSymbolAddress((void**)&XQh, g_XQh); cudaGetSymbolAddress((void**)&XQl, g_XQl);
    cudaGetSymbolAddress((void**)&XKh, g_XKh); cudaGetSymbolAddress((void**)&XKl, g_XKl);
    cudaGetSymbolAddress((void**)&XVh, g_XVh); cudaGetSymbolAddress((void**)&XVl, g_XVl);
    cudaGetSymbolAddress((void**)&Wqh, g_Wqh); cudaGetSymbolAddress((void**)&Wql, g_Wql);
    cudaGetSymbolAddress((void**)&Wkh, g_Wkh); cudaGetSymbolAddress((void**)&Wkl, g_Wkl);
    cudaGetSymbolAddress((void**)&Wvh, g_Wvh); cudaGetSymbolAddress((void**)&Wvl, g_Wvl);
    cudaGetSymbolAddress((void**)&Woh, g_Woh); cudaGetSymbolAddress((void**)&Wol, g_Wol);
    cudaGetSymbolAddress((void**)&Qh, g_Qh);   cudaGetSymbolAddress((void**)&Ql, g_Ql);
    cudaGetSymbolAddress((void**)&Kh, g_Kh);   cudaGetSymbolAddress((void**)&Kl, g_Kl);
    cudaGetSymbolAddress((void**)&Vth, g_Vth); cudaGetSymbolAddress((void**)&Vtl, g_Vtl);
    cudaGetSymbolAddress((void**)&Chp, g_Ch);  cudaGetSymbolAddress((void**)&Clp, g_Cl);
    cudaGetSymbolAddress((void**)&Ap, g_attn);

    float* attn = ((size_t)out_size >= OUT_ELEMS + ATT_ELEMS) ? (out + OUT_ELEMS) : Ap;

    const int SM128 = 2 * (2 * 128 * 80 + 2 * 128 * 80);  // 81920
    const int SM64  = 2 * (2 * 128 * 80 + 2 * 64 * 80);   // 61440
    const int SMQK  = 2 * (32 * 144) + 2 * (2 * 128 * 144) + 32 * 1028 * 4 + 128; // 214656
    cudaFuncSetAttribute(proj_qkv, cudaFuncAttributeMaxDynamicSharedMemorySize, SM128);
    cudaFuncSetAttribute(gemm_pp<128, 0, true>, cudaFuncAttributeMaxDynamicSharedMemorySize, SM128);
    cudaFuncSetAttribute(gemm_pp<64, 3, false>, cudaFuncAttributeMaxDynamicSharedMemorySize, SM64);
    cudaFuncSetAttribute(qk_softmax, cudaFuncAttributeMaxDynamicSharedMemorySize, SMQK);

    // 1) split all inputs to bf16 hi/lo
    split_all<<<16384, 256>>>(query, key, value, Wq, Wk, Wv, Wo);

    dim3 blk(512);

    // 2) Q/K/V projections in ONE launch (gridDim.z = 3)
    proj_qkv<<<dim3(8, 32, 3), blk, SM128>>>(
        XQh, XQl, XKh, XKl, XVh, XVl,
        Wqh, Wql, Wkh, Wkl, Wvh, Wvl,
        Qh, Ql, Kh, Kl, Vth, Vtl);

    // 3) fused scores + softmax -> attn (streaming writes)
    qk_softmax<<<dim3(32, 64), blk, SMQK>>>(Qh, Ql, Kh, Kl, attn);

    // 4) ctx = attn @ V  (streaming attn reads)
    gemm_pp<64, 3, false><<<dim3(1, 8, BB * HH), blk, SM64>>>(
        nullptr, nullptr, attn, Vth, Vtl, nullptr, Chp, Clp,
        SS, SS, SS, 0, (long)SS * SS, (long)DD * SS, 0, 1.0f);

    // 5) out = ctx @ Wo^T
    gemm_pp<128, 0, true><<<dim3(8, 32, 1), blk, SM128>>>(
        Chp, Clp, nullptr, Woh, Wol, out, nullptr, nullptr,
        DMM, DMM, DMM, DMM, 0, 0, 0, 1.0f);
}

// round 15
// speedup vs baseline: 1.0263x; 1.0093x over previous
#include <cuda_runtime.h>
#include <cuda_bf16.h>
#include <cstdint>

#define BB 4
#define SS 1024
#define HH 16
#define DD 64
#define DMM 1024

static const size_t OUT_ELEMS = (size_t)BB * SS * DMM;        // 4194304
static const size_t ATT_ELEMS = (size_t)BB * HH * SS * SS;    // 67108864

#define ACT_N (4096 * 1024)
#define W_N   (1024 * 1024)

// Scratch (__device__ globals) — bf16 hi/lo pairs
__device__ __align__(16) __nv_bfloat16 g_XQh[ACT_N], g_XQl[ACT_N];
__device__ __align__(16) __nv_bfloat16 g_XKh[ACT_N], g_XKl[ACT_N];
__device__ __align__(16) __nv_bfloat16 g_XVh[ACT_N], g_XVl[ACT_N];
__device__ __align__(16) __nv_bfloat16 g_Wqh[W_N], g_Wql[W_N];
__device__ __align__(16) __nv_bfloat16 g_Wkh[W_N], g_Wkl[W_N];
__device__ __align__(16) __nv_bfloat16 g_Wvh[W_N], g_Wvl[W_N];
__device__ __align__(16) __nv_bfloat16 g_Woh[W_N], g_Wol[W_N];
__device__ __align__(16) __nv_bfloat16 g_Qh[ACT_N], g_Ql[ACT_N];   // [bh][s][d]
__device__ __align__(16) __nv_bfloat16 g_Kh[ACT_N], g_Kl[ACT_N];   // [bh][s][d]
__device__ __align__(16) __nv_bfloat16 g_Vth[ACT_N], g_Vtl[ACT_N]; // [bh][d][s]
__device__ __align__(16) __nv_bfloat16 g_Ch[ACT_N], g_Cl[ACT_N];   // ctx [b*s][dm]
__device__ float g_attn[(size_t)BB * HH * SS * SS];                 // fallback

// ---------------------------------------------------------------------------
__device__ __forceinline__ uint32_t smem_u32(const void* p) {
    uint32_t a;
    asm("{ .reg .u64 t; cvta.to.shared.u64 t, %1; cvt.u32.u64 %0, t; }" : "=r"(a) : "l"(p));
    return a;
}
__device__ __forceinline__ void ldsm4(uint32_t* r, uint32_t addr) {
    asm volatile("ldmatrix.sync.aligned.m8n8.x4.shared.b16 {%0,%1,%2,%3}, [%4];"
        : "=r"(r[0]), "=r"(r[1]), "=r"(r[2]), "=r"(r[3]) : "r"(addr));
}
__device__ __forceinline__ void mma16816(float* d, const uint32_t* a, uint32_t b0, uint32_t b1) {
    asm volatile("mma.sync.aligned.m16n8k16.row.col.f32.bf16.bf16.f32 "
        "{%0,%1,%2,%3}, {%4,%5,%6,%7}, {%8,%9}, {%0,%1,%2,%3};"
        : "+f"(d[0]), "+f"(d[1]), "+f"(d[2]), "+f"(d[3])
        : "r"(a[0]), "r"(a[1]), "r"(a[2]), "r"(a[3]), "r"(b0), "r"(b1));
}
__device__ __forceinline__ void cp16(uint32_t s, const void* g) {
    asm volatile("cp.async.cg.shared.global [%0], [%1], 16;" :: "r"(s), "l"(g));
}
#define CP_COMMIT() asm volatile("cp.async.commit_group;" ::: "memory")
#define CP_WAIT(N)  asm volatile("cp.async.wait_group %0;" :: "n"(N) : "memory")
#define STS64(addr, r0, r1) \
    asm volatile("st.shared.v2.b32 [%0], {%1,%2};" :: "r"(addr), "r"(r0), "r"(r1) : "memory")

__device__ __forceinline__ void cvt_pair(float x, float y, uint32_t& hi, uint32_t& lo) {
    __nv_bfloat16 hx = __float2bfloat16(x), hy = __float2bfloat16(y);
    float rx = x - __bfloat162float(hx), ry = y - __bfloat162float(hy);
    __nv_bfloat16 lx = __float2bfloat16(rx), ly = __float2bfloat16(ry);
    hi = ((uint32_t)__bfloat16_as_ushort(hy) << 16) | __bfloat16_as_ushort(hx);
    lo = ((uint32_t)__bfloat16_as_ushort(ly) << 16) | __bfloat16_as_ushort(lx);
}

// ---------------------------------------------------------------------------
// Split fp32 -> bf16 hi/lo for all 7 inputs.
// ---------------------------------------------------------------------------
__global__ void __launch_bounds__(256) split_all(
    const float* q, const float* k, const float* v,
    const float* wq, const float* wk, const float* wv, const float* wo)
{
    long i4 = (long)blockIdx.x * blockDim.x + threadIdx.x;   // float4 index
    const float* src; __nv_bfloat16 *dh, *dl; long rel;
    const long M1 = 1048576, Q4 = 262144;
    if (i4 < M1)            { src = q;  dh = g_XQh; dl = g_XQl; rel = i4; }
    else if (i4 < 2*M1)     { src = k;  dh = g_XKh; dl = g_XKl; rel = i4 - M1; }
    else if (i4 < 3*M1)     { src = v;  dh = g_XVh; dl = g_XVl; rel = i4 - 2*M1; }
    else if (i4 < 3*M1+Q4)  { src = wq; dh = g_Wqh; dl = g_Wql; rel = i4 - 3*M1; }
    else if (i4 < 3*M1+2*Q4){ src = wk; dh = g_Wkh; dl = g_Wkl; rel = i4 - 3*M1 - Q4; }
    else if (i4 < 3*M1+3*Q4){ src = wv; dh = g_Wvh; dl = g_Wvl; rel = i4 - 3*M1 - 2*Q4; }
    else                    { src = wo; dh = g_Woh; dl = g_Wol; rel = i4 - 3*M1 - 3*Q4; }
    float4 x = ((const float4*)src)[rel];
    uint32_t h0, l0, h1, l1;
    cvt_pair(x.x, x.y, h0, l0);
    cvt_pair(x.z, x.w, h1, l1);
    ((uint2*)dh)[rel] = make_uint2(h0, h1);
    ((uint2*)dl)[rel] = make_uint2(l0, l1);
}

// ---------------------------------------------------------------------------
// Combined Q/K projection GEMM (R12 proven body): one launch, gridDim.z = 2.
// ---------------------------------------------------------------------------
__global__ void __launch_bounds__(512, 2) proj_qk(
    const __nv_bfloat16* __restrict__ XQh, const __nv_bfloat16* __restrict__ XQl,
    const __nv_bfloat16* __restrict__ XKh, const __nv_bfloat16* __restrict__ XKl,
    const __nv_bfloat16* __restrict__ Wqh, const __nv_bfloat16* __restrict__ Wql,
    const __nv_bfloat16* __restrict__ Wkh, const __nv_bfloat16* __restrict__ Wkl,
    __nv_bfloat16* __restrict__ Qh, __nv_bfloat16* __restrict__ Ql,
    __nv_bfloat16* __restrict__ Kh, __nv_bfloat16* __restrict__ Kl)
{
    extern __shared__ char smem[];
    constexpr int RB  = 80;
    constexpr int ASZ = 128 * RB;
    constexpr int BSZ = 128 * RB;
    constexpr int STG = 2 * ASZ + 2 * BSZ;

    const int z = blockIdx.z;
    const __nv_bfloat16* Ah = (z == 0) ? XQh : XKh;
    const __nv_bfloat16* Al = (z == 0) ? XQl : XKl;
    const __nv_bfloat16* Bh = (z == 0) ? Wqh : Wkh;
    const __nv_bfloat16* Bl = (z == 0) ? Wql : Wkl;
    __nv_bfloat16* Ch = (z == 0) ? Qh : Kh;
    __nv_bfloat16* Cl = (z == 0) ? Ql : Kl;

    const uint32_t sb = smem_u32(smem);
    const int tid = threadIdx.x, lane = tid & 31, wid = tid >> 5;
    const int wm = (wid & 3) * 32, wn = (wid >> 2) * 32;
    const int m0 = blockIdx.y * 128, n0 = blockIdx.x * 128;

    Ah += (long)m0 * DMM;
    Al += (long)m0 * DMM;
    Bh += (long)n0 * DMM;
    Bl += (long)n0 * DMM;

    float acc[2][4][4];
#pragma unroll
    for (int mt = 0; mt < 2; ++mt)
#pragma unroll
        for (int nt = 0; nt < 4; ++nt)
#pragma unroll
            for (int j = 0; j < 4; ++j) acc[mt][nt][j] = 0.f;

    auto CPA = [&](int i, int st) {
        int r = tid >> 2, g = tid & 3;
        uint32_t d = sb + (uint32_t)st * STG + (uint32_t)r * RB + (uint32_t)g * 16;
        cp16(d, Ah + (long)r * DMM + i * 32 + g * 8);
        cp16(d + ASZ, Al + (long)r * DMM + i * 32 + g * 8);
    };
    auto CPB = [&](int i, int st) {
        int r = tid >> 2, g = tid & 3;
        uint32_t d = sb + (uint32_t)st * STG + 2 * ASZ + (uint32_t)r * RB + (uint32_t)g * 16;
        cp16(d, Bh + (long)r * DMM + i * 32 + g * 8);
        cp16(d + BSZ, Bl + (long)r * DMM + i * 32 + g * 8);
    };

    const int NC = DMM / 32;
    CPA(0, 0); CPB(0, 0); CP_COMMIT();

    const int aRowOff = (lane & 7) + ((lane >> 3) & 1) * 8;
    const uint32_t aColOff = (uint32_t)((lane >> 4) * 8);
    const int bRowOff = (lane & 7) + ((lane >> 4) & 1) * 8;
    const uint32_t bColOff = (uint32_t)(((lane >> 3) & 1) * 8);

    for (int i = 0; i < NC; ++i) {
        const int s = i & 1;
        if (i + 1 < NC) { CPA(i + 1, s ^ 1); CPB(i + 1, s ^ 1); CP_COMMIT(); CP_WAIT(1); }
        else            { CP_WAIT(0); }
        __syncthreads();

        const uint32_t aB = sb + (uint32_t)s * STG;
        const uint32_t bB = aB + 2 * ASZ;
#pragma unroll
        for (int ks = 0; ks < 2; ++ks) {
            uint32_t ah[2][4], al[2][4];
            const uint32_t ac = (aColOff + ks * 16) * 2;
#pragma unroll
            for (int mt = 0; mt < 2; ++mt) {
                uint32_t ad = aB + (uint32_t)(wm + mt * 16 + aRowOff) * RB + ac;
                ldsm4(ah[mt], ad);
                ldsm4(al[mt], ad + ASZ);
            }
            uint32_t bh[2][4], bl[2][4];
            const uint32_t bc = (bColOff + ks * 16) * 2;
#pragma unroll
            for (int p = 0; p < 2; ++p) {
                uint32_t bd = bB + (uint32_t)(wn + p * 16 + bRowOff) * RB + bc;
                ldsm4(bh[p], bd);
                ldsm4(bl[p], bd + BSZ);
            }
#pragma unroll
            for (int mt = 0; mt < 2; ++mt)
#pragma unroll
                for (int p = 0; p < 2; ++p) {
                    mma16816(acc[mt][2*p],   ah[mt], bh[p][0], bh[p][1]);
                    mma16816(acc[mt][2*p+1], ah[mt], bh[p][2], bh[p][3]);
                }
#pragma unroll
            for (int mt = 0; mt < 2; ++mt)
#pragma unroll
                for (int p = 0; p < 2; ++p) {
                    mma16816(acc[mt][2*p],   al[mt], bh[p][0], bh[p][1]);
                    mma16816(acc[mt][2*p+1], al[mt], bh[p][2], bh[p][3]);
                }
#pragma unroll
            for (int mt = 0; mt < 2; ++mt)
#pragma unroll
                for (int p = 0; p < 2; ++p) {
                    mma16816(acc[mt][2*p],   ah[mt], bl[p][0], bl[p][1]);
                    mma16816(acc[mt][2*p+1], ah[mt], bl[p][2], bl[p][3]);
                }
        }
        __syncthreads();
    }

#pragma unroll
    for (int mt = 0; mt < 2; ++mt)
#pragma unroll
        for (int nt = 0; nt < 4; ++nt) {
#pragma unroll
            for (int half = 0; half < 2; ++half) {
                int m = m0 + wm + mt * 16 + (lane >> 2) + half * 8;
                int n = n0 + wn + nt * 8 + (lane & 3) * 2;
                float x = acc[mt][nt][half * 2], y = acc[mt][nt][half * 2 + 1];
                int h = n >> 6, d = n & 63, b = m >> 10, sI = m & 1023;
                long idx = ((long)(b * HH + h) * SS + sI) * DD + d;
                uint32_t hi, lo;
                cvt_pair(x, y, hi, lo);
                *(uint32_t*)(Ch + idx) = hi;
                *(uint32_t*)(Cl + idx) = lo;
            }
        }
}

// ---------------------------------------------------------------------------
// FAT kernel: blockIdx.x < 256  -> V projection (XV@Wv -> V^T pairs)
//             blockIdx.x >= 256 -> fused QK^T + softmax (R10 proven body)
// Both at 512 threads; smem = 214656 (1 CTA/SM). V-proj CTAs fill the
// tensor-pipe idle time of the bandwidth-bound qk CTAs.
// ---------------------------------------------------------------------------
__global__ void __launch_bounds__(512) vproj_qk(
    const __nv_bfloat16* __restrict__ XVh, const __nv_bfloat16* __restrict__ XVl,
    const __nv_bfloat16* __restrict__ Wvh, const __nv_bfloat16* __restrict__ Wvl,
    __nv_bfloat16* __restrict__ Vth, __nv_bfloat16* __restrict__ Vtl,
    const __nv_bfloat16* __restrict__ Qh, const __nv_bfloat16* __restrict__ Ql,
    const __nv_bfloat16* __restrict__ Kh, const __nv_bfloat16* __restrict__ Kl,
    float* __restrict__ attn)
{
    extern __shared__ char smem[];
    const uint32_t sb = smem_u32(smem);
    const int tid = threadIdx.x, lane = tid & 31, wid = tid >> 5;

    if (blockIdx.x < 256) {
        // ================= V projection (mode 2 epilogue) =================
        constexpr int RB  = 80;
        constexpr int ASZ = 128 * RB;
        constexpr int BSZ = 128 * RB;
        constexpr int STG = 2 * ASZ + 2 * BSZ;

        const int id = blockIdx.x;
        const int m0 = (id >> 3) * 128, n0 = (id & 7) * 128;
        const int wm = (wid & 3) * 32, wn = (wid >> 2) * 32;

        const __nv_bfloat16* Ah = XVh + (long)m0 * DMM;
        const __nv_bfloat16* Al = XVl + (long)m0 * DMM;
        const __nv_bfloat16* Bh = Wvh + (long)n0 * DMM;
        const __nv_bfloat16* Bl = Wvl + (long)n0 * DMM;

        float acc[2][4][4];
#pragma unroll
        for (int mt = 0; mt < 2; ++mt)
#pragma unroll
            for (int nt = 0; nt < 4; ++nt)
#pragma unroll
                for (int j = 0; j < 4; ++j) acc[mt][nt][j] = 0.f;

        auto CPA = [&](int i, int st) {
            int r = tid >> 2, g = tid & 3;
            uint32_t d = sb + (uint32_t)st * STG + (uint32_t)r * RB + (uint32_t)g * 16;
            cp16(d, Ah + (long)r * DMM + i * 32 + g * 8);
            cp16(d + ASZ, Al + (long)r * DMM + i * 32 + g * 8);
        };
        auto CPB = [&](int i, int st) {
            int r = tid >> 2, g = tid & 3;
            uint32_t d = sb + (uint32_t)st * STG + 2 * ASZ + (uint32_t)r * RB + (uint32_t)g * 16;
            cp16(d, Bh + (long)r * DMM + i * 32 + g * 8);
            cp16(d + BSZ, Bl + (long)r * DMM + i * 32 + g * 8);
        };

        const int NC = DMM / 32;
        CPA(0, 0); CPB(0, 0); CP_COMMIT();

        const int aRowOff = (lane & 7) + ((lane >> 3) & 1) * 8;
        const uint32_t aColOff = (uint32_t)((lane >> 4) * 8);
        const int bRowOff = (lane & 7) + ((lane >> 4) & 1) * 8;
        const uint32_t bColOff = (uint32_t)(((lane >> 3) & 1) * 8);

        for (int i = 0; i < NC; ++i) {
            const int s = i & 1;
            if (i + 1 < NC) { CPA(i + 1, s ^ 1); CPB(i + 1, s ^ 1); CP_COMMIT(); CP_WAIT(1); }
            else            { CP_WAIT(0); }
            __syncthreads();

            const uint32_t aB = sb + (uint32_t)s * STG;
            const uint32_t bB = aB + 2 * ASZ;
#pragma unroll
            for (int ks = 0; ks < 2; ++ks) {
                uint32_t ah[2][4], al[2][4];
                const uint32_t ac = (aColOff + ks * 16) * 2;
#pragma unroll
                for (int mt = 0; mt < 2; ++mt) {
                    uint32_t ad = aB + (uint32_t)(wm + mt * 16 + aRowOff) * RB + ac;
                    ldsm4(ah[mt], ad);
                    ldsm4(al[mt], ad + ASZ);
                }
                uint32_t bh[2][4], bl[2][4];
                const uint32_t bc = (bColOff + ks * 16) * 2;
#pragma unroll
                for (int p = 0; p < 2; ++p) {
                    uint32_t bd = bB + (uint32_t)(wn + p * 16 + bRowOff) * RB + bc;
                    ldsm4(bh[p], bd);
                    ldsm4(bl[p], bd + BSZ);
                }
#pragma unroll
                for (int mt = 0; mt < 2; ++mt)
#pragma unroll
                    for (int p = 0; p < 2; ++p) {
                        mma16816(acc[mt][2*p],   ah[mt], bh[p][0], bh[p][1]);
                        mma16816(acc[mt][2*p+1], ah[mt], bh[p][2], bh[p][3]);
                    }
#pragma unroll
                for (int mt = 0; mt < 2; ++mt)
#pragma unroll
                    for (int p = 0; p < 2; ++p) {
                        mma16816(acc[mt][2*p],   al[mt], bh[p][0], bh[p][1]);
                        mma16816(acc[mt][2*p+1], al[mt], bh[p][2], bh[p][3]);
                    }
#pragma unroll
                for (int mt = 0; mt < 2; ++mt)
#pragma unroll
                    for (int p = 0; p < 2; ++p) {
                        mma16816(acc[mt][2*p],   ah[mt], bl[p][0], bl[p][1]);
                        mma16816(acc[mt][2*p+1], ah[mt], bl[p][2], bl[p][3]);
                    }
            }
            __syncthreads();
        }

#pragma unroll
        for (int mt = 0; mt < 2; ++mt)
#pragma unroll
            for (int nt = 0; nt < 4; ++nt) {
#pragma unroll
                for (int half = 0; half < 2; ++half) {
                    int m = m0 + wm + mt * 16 + (lane >> 2) + half * 8;
                    int n = n0 + wn + nt * 8 + (lane & 3) * 2;
                    float x = acc[mt][nt][half * 2], y = acc[mt][nt][half * 2 + 1];
                    int h = n >> 6, d = n & 63, b = m >> 10, sI = m & 1023;
                    long base = ((long)(b * HH + h) * DD + d) * SS + sI;
                    __nv_bfloat16 xh = __float2bfloat16(x);
                    __nv_bfloat16 xl = __float2bfloat16(x - __bfloat162float(xh));
                    __nv_bfloat16 yh = __float2bfloat16(y);
                    __nv_bfloat16 yl = __float2bfloat16(y - __bfloat162float(yh));
                    Vth[base] = xh; Vtl[base] = xl;
                    Vth[base + SS] = yh; Vtl[base + SS] = yl;
                }
            }
        return;
    }

    // ================= fused QK^T + softmax (R10 proven) =================
    {
        constexpr int QRB  = 144;
        constexpr int QSZ  = 32 * QRB;
        constexpr int KSZ  = 128 * QRB;
        constexpr int KSTG = 2 * KSZ;
        constexpr int SOFF = 2 * QSZ + 2 * KSTG;
        constexpr int SROW = 1028;

        const uint32_t sQ = sb;
        const uint32_t sK = sb + 2 * QSZ;
        float* Sp = reinterpret_cast<float*>(smem + SOFF);
        float* Ip = reinterpret_cast<float*>(smem + SOFF + 32 * SROW * 4);

        const int id = blockIdx.x - 256;
        const int q0 = (id & 31) * 32;
        const int bh = id >> 5;
        const long qbase = ((long)bh * SS + q0) * DD;
        const long kbase = (long)bh * SS * DD;

        {
            int p = tid >> 8, rem = tid & 255;
            int r = rem >> 3, g = rem & 7;
            const __nv_bfloat16* src = (p ? Ql : Qh) + qbase + (long)r * DD + g * 8;
            cp16(sQ + (uint32_t)p * QSZ + (uint32_t)r * QRB + (uint32_t)g * 16, src);
        }
        auto CPK = [&](int nt, int st) {
#pragma unroll
            for (int j = 0; j < 4; ++j) {
                int idx = tid + j * 512;
                int p = idx >> 10, rem = idx & 1023;
                int r = rem >> 3, g = rem & 7;
                const __nv_bfloat16* src = (p ? Kl : Kh) + kbase + (long)(nt * 128 + r) * DD + g * 8;
                cp16(sK + (uint32_t)st * KSTG + (uint32_t)p * KSZ + (uint32_t)r * QRB + (uint32_t)g * 16, src);
            }
        };
        CPK(0, 0);
        CP_COMMIT();

        const int wm = (wid & 1) * 16, wn = (wid >> 1) * 16;
        const int aRowOff = (lane & 7) + ((lane >> 3) & 1) * 8;
        const uint32_t aColOff = (uint32_t)((lane >> 4) * 8);
        const int bRowOff = (lane & 7) + ((lane >> 4) & 1) * 8;
        const uint32_t bColOff = (uint32_t)(((lane >> 3) & 1) * 8);

        for (int nt = 0; nt < 8; ++nt) {
            const int s = nt & 1;
            if (nt + 1 < 8) { CPK(nt + 1, s ^ 1); CP_COMMIT(); CP_WAIT(1); }
            else            { CP_WAIT(0); }
            __syncthreads();

            float acc[2][4];
#pragma unroll
            for (int j = 0; j < 2; ++j)
#pragma unroll
                for (int v = 0; v < 4; ++v) acc[j][v] = 0.f;

            const uint32_t kB = sK + (uint32_t)s * KSTG;
#pragma unroll
            for (int ks = 0; ks < 4; ++ks) {
                uint32_t ah[4], al[4];
                const uint32_t ac = (aColOff + ks * 16) * 2;
                uint32_t ad = sQ + (uint32_t)(wm + aRowOff) * QRB + ac;
                ldsm4(ah, ad);
                ldsm4(al, ad + QSZ);
                uint32_t bhf[4], blf[4];
                const uint32_t bc = (bColOff + ks * 16) * 2;
                uint32_t bd = kB + (uint32_t)(wn + bRowOff) * QRB + bc;
                ldsm4(bhf, bd);
                ldsm4(blf, bd + KSZ);
                mma16816(acc[0], ah, bhf[0], bhf[1]);
                mma16816(acc[1], ah, bhf[2], bhf[3]);
                mma16816(acc[0], al, bhf[0], bhf[1]);
                mma16816(acc[1], al, bhf[2], bhf[3]);
                mma16816(acc[0], ah, blf[0], blf[1]);
                mma16816(acc[1], ah, blf[2], blf[3]);
            }

            const int m = wm + (lane >> 2);
#pragma unroll
            for (int j = 0; j < 2; ++j) {
                int c = nt * 128 + wn + j * 8 + (lane & 3) * 2;
                float2 e01 = make_float2(__expf(acc[j][0] * 0.125f), __expf(acc[j][1] * 0.125f));
                float2 e23 = make_float2(__expf(acc[j][2] * 0.125f), __expf(acc[j][3] * 0.125f));
                *(float2*)&Sp[(long)m * SROW + c]       = e01;
                *(float2*)&Sp[(long)(m + 8) * SROW + c] = e23;
            }
            __syncthreads();
        }

        {
            int r = tid >> 4, j = tid & 15;
            float sum = 0.f;
#pragma unroll
            for (int k = 0; k < 16; ++k) {
                float4 v = *(float4*)&Sp[(long)r * SROW + j * 4 + k * 64];
                sum += (v.x + v.y) + (v.z + v.w);
            }
            sum += __shfl_xor_sync(0xffffffffu, sum, 1);
            sum += __shfl_xor_sync(0xffffffffu, sum, 2);
            sum += __shfl_xor_sync(0xffffffffu, sum, 4);
            sum += __shfl_xor_sync(0xffffffffu, sum, 8);
            if (j == 0) Ip[r] = 1.0f / sum;
        }
        __syncthreads();

        {
            int r = tid >> 4, j = tid & 15;
            float inv = Ip[r];
            float* dst = attn + ((long)bh * SS + q0 + r) * SS;
#pragma unroll
            for (int k = 0; k < 16; ++k) {
                int c = j * 4 + k * 64;
                float4 v = *(float4*)&Sp[(long)r * SROW + c];
                v.x *= inv; v.y *= inv; v.z *= inv; v.w *= inv;
                *(float4*)&dst[c] = v;
            }
        }
    }
}

// ---------------------------------------------------------------------------
// Split-precision bf16 HMMA GEMM (R8/R10 proven: 512 thr, 2 CTAs/SM, 2-stage).
// MODE: 0 fp32 row-major (*scale); 3 ctx pair out [b*s][dm] (z=bh, n=d)
// PAIRA=false: A fp32 split in-loader.
// ---------------------------------------------------------------------------
template<int NT, int MODE, bool PAIRA>
__global__ void __launch_bounds__(512, 2) gemm_pp(
    const __nv_bfloat16* __restrict__ Ah, const __nv_bfloat16* __restrict__ Al,
    const float* __restrict__ Af,
    const __nv_bfloat16* __restrict__ Bh, const __nv_bfloat16* __restrict__ Bl,
    float* __restrict__ Cf, __nv_bfloat16* __restrict__ Ch, __nv_bfloat16* __restrict__ Cl,
    int K, int lda, int ldb, int ldc,
    long sAz, long sBz, long sCz, float scale)
{
    extern __shared__ char smem[];
    constexpr int RB  = 80;
    constexpr int ASZ = 128 * RB;
    constexpr int BSZ = NT * RB;
    constexpr int STG = 2 * ASZ + 2 * BSZ;
    constexpr int NTP = (NT == 128) ? 2 : 1;
    constexpr int WNE = (NT == 128) ? 32 : 16;

    const uint32_t sb = smem_u32(smem);
    const int tid = threadIdx.x, lane = tid & 31, wid = tid >> 5;
    const int wm = (wid & 3) * 32, wn = (wid >> 2) * WNE;
    const int m0 = blockIdx.y * 128, n0 = blockIdx.x * NT;

    if (PAIRA) {
        Ah += (long)blockIdx.z * sAz + (long)m0 * lda;
        Al += (long)blockIdx.z * sAz + (long)m0 * lda;
    } else {
        Af += (long)blockIdx.z * sAz + (long)m0 * lda;
    }
    Bh += (long)blockIdx.z * sBz + (long)n0 * ldb;
    Bl += (long)blockIdx.z * sBz + (long)n0 * ldb;

    float acc[2][2 * NTP][4];
#pragma unroll
    for (int mt = 0; mt < 2; ++mt)
#pragma unroll
        for (int nt = 0; nt < 2 * NTP; ++nt)
#pragma unroll
            for (int j = 0; j < 4; ++j) acc[mt][nt][j] = 0.f;

    float4 ra[2];

    auto CPA = [&](int i, int st) {
        int r = tid >> 2, g = tid & 3;
        uint32_t d = sb + (uint32_t)st * STG + (uint32_t)r * RB + (uint32_t)g * 16;
        cp16(d, Ah + (long)r * lda + i * 32 + g * 8);
        cp16(d + ASZ, Al + (long)r * lda + i * 32 + g * 8);
    };
    auto CPB = [&](int i, int st) {
        if (NT == 128 || tid < 256) {
            int r = tid >> 2, g = tid & 3;
            uint32_t d = sb + (uint32_t)st * STG + 2 * ASZ + (uint32_t)r * RB + (uint32_t)g * 16;
            cp16(d, Bh + (long)r * ldb + i * 32 + g * 8);
            cp16(d + BSZ, Bl + (long)r * ldb + i * 32 + g * 8);
        }
    };
    auto LDGA = [&](int i) {
#pragma unroll
        for (int t = 0; t < 2; ++t) {
            int c = tid + t * 512, r = c >> 3, g = c & 7;
            ra[t] = *(const float4*)(Af + (long)r * lda + i * 32 + g * 4);
        }
    };
    auto STSA = [&](int st) {
#pragma unroll
        for (int t = 0; t < 2; ++t) {
            int c = tid + t * 512, r = c >> 3, g = c & 7;
            uint32_t h0, l0, h1, l1;
            cvt_pair(ra[t].x, ra[t].y, h0, l0);
            cvt_pair(ra[t].z, ra[t].w, h1, l1);
            uint32_t d = sb + (uint32_t)st * STG + (uint32_t)r * RB + (uint32_t)g * 8;
            STS64(d, h0, h1);
            STS64(d + ASZ, l0, l1);
        }
    };

    const int NC = K / 32;
    if (PAIRA) CPA(0, 0); else LDGA(0);
    CPB(0, 0);
    CP_COMMIT();
    if (!PAIRA) STSA(0);

    const int aRowOff = (lane & 7) + ((lane >> 3) & 1) * 8;
    const uint32_t aColOff = (uint32_t)((lane >> 4) * 8);
    const int bRowOff = (lane & 7) + ((lane >> 4) & 1) * 8;
    const uint32_t bColOff = (uint32_t)(((lane >> 3) & 1) * 8);

    for (int i = 0; i < NC; ++i) {
        const int s = i & 1;
        if (i + 1 < NC) {
            if (PAIRA) CPA(i + 1, s ^ 1);
            else       LDGA(i + 1);
            CPB(i + 1, s ^ 1);
            CP_COMMIT();
            CP_WAIT(1);
        } else {
            CP_WAIT(0);
        }
        __syncthreads();

        const uint32_t aB = sb + (uint32_t)s * STG;
        const uint32_t bB = aB + 2 * ASZ;
#pragma unroll
        for (int ks = 0; ks < 2; ++ks) {
            uint32_t ah[2][4], al[2][4];
            const uint32_t ac = (aColOff + ks * 16) * 2;
#pragma unroll
            for (int mt = 0; mt < 2; ++mt) {
                uint32_t ad = aB + (uint32_t)(wm + mt * 16 + aRowOff) * RB + ac;
                ldsm4(ah[mt], ad);
                ldsm4(al[mt], ad + ASZ);
            }
            uint32_t bh[NTP][4], bl[NTP][4];
            const uint32_t bc = (bColOff + ks * 16) * 2;
#pragma unroll
            for (int p = 0; p < NTP; ++p) {
                uint32_t bd = bB + (uint32_t)(wn + p * 16 + bRowOff) * RB + bc;
                ldsm4(bh[p], bd);
                ldsm4(bl[p], bd + BSZ);
            }
#pragma unroll
            for (int mt = 0; mt < 2; ++mt)
#pragma unroll
                for (int p = 0; p < NTP; ++p) {
                    mma16816(acc[mt][2*p],   ah[mt], bh[p][0], bh[p][1]);
                    mma16816(acc[mt][2*p+1], ah[mt], bh[p][2], bh[p][3]);
                }
#pragma unroll
            for (int mt = 0; mt < 2; ++mt)
#pragma unroll
                for (int p = 0; p < NTP; ++p) {
                    mma16816(acc[mt][2*p],   al[mt], bh[p][0], bh[p][1]);
                    mma16816(acc[mt][2*p+1], al[mt], bh[p][2], bh[p][3]);
                }
#pragma unroll
            for (int mt = 0; mt < 2; ++mt)
#pragma unroll
                for (int p = 0; p < NTP; ++p) {
                    mma16816(acc[mt][2*p],   ah[mt], bl[p][0], bl[p][1]);
                    mma16816(acc[mt][2*p+1], ah[mt], bl[p][2], bl[p][3]);
                }
        }
        if (!PAIRA && i + 1 < NC) STSA(s ^ 1);
        __syncthreads();
    }

    auto emit = [&](int m, int n, float x, float y) {
        if (MODE == 0) {
            float* p = Cf + (long)blockIdx.z * sCz + (long)m * ldc + n;
            *(float2*)p = make_float2(x * scale, y * scale);
        } else {
            int z = blockIdx.z, b = z >> 4, h = z & 15;
            long idx = ((long)(b * SS + m)) * DMM + h * DD + n;
            uint32_t hi, lo;
            cvt_pair(x, y, hi, lo);
            *(uint32_t*)(Ch + idx) = hi;
            *(uint32_t*)(Cl + idx) = lo;
        }
    };

#pragma unroll
    for (int mt = 0; mt < 2; ++mt)
#pragma unroll
        for (int nt = 0; nt < 2 * NTP; ++nt) {
            int m = m0 + wm + mt * 16 + (lane >> 2);
            int n = n0 + wn + nt * 8 + (lane & 3) * 2;
            emit(m,     n, acc[mt][nt][0], acc[mt][nt][1]);
            emit(m + 8, n, acc[mt][nt][2], acc[mt][nt][3]);
        }
}

// ---------------------------------------------------------------------------
extern "C" void kernel_launch(void* const* d_in, const int* in_sizes, int n_in,
                              void* d_out, int out_size)
{
    const float* query = (const float*)d_in[0];
    const float* key   = (const float*)d_in[1];
    const float* value = (const float*)d_in[2];
    const float* Wq    = (const float*)d_in[3];
    const float* Wk    = (const float*)d_in[4];
    const float* Wv    = (const float*)d_in[5];
    const float* Wo    = (const float*)d_in[6];
    float* out = (float*)d_out;

    __nv_bfloat16 *XQh, *XQl, *XKh, *XKl, *XVh, *XVl;
    __nv_bfloat16 *Wqh, *Wql, *Wkh, *Wkl, *Wvh, *Wvl, *Woh, *Wol;
    __nv_bfloat16 *Qh, *Ql, *Kh, *Kl, *Vth, *Vtl, *Chp, *Clp;
    float* Ap;
    cudaGetSymbolAddress((void**)&XQh, g_XQh); cudaGetSymbolAddress((void**)&XQl, g_XQl);
    cudaGetSymbolAddress((void**)&XKh, g_XKh); cudaGetSymbolAddress((void**)&XKl, g_XKl);
    cudaGetSymbolAddress((void**)&XVh, g_XVh); cudaGetSymbolAddress((void**)&XVl, g_XVl);
    cudaGetSymbolAddress((void**)&Wqh, g_Wqh); cudaGetSymbolAddress((void**)&Wql, g_Wql);
    cudaGetSymbolAddress((void**)&Wkh, g_Wkh); cudaGetSymbolAddress((void**)&Wkl, g_Wkl);
    cudaGetSymbolAddress((void**)&Wvh, g_Wvh); cudaGetSymbolAddress((void**)&Wvl, g_Wvl);
    cudaGetSymbolAddress((void**)&Woh, g_Woh); cudaGetSymbolAddress((void**)&Wol, g_Wol);
    cudaGetSymbolAddress((void**)&Qh, g_Qh);   cudaGetSymbolAddress((void**)&Ql, g_Ql);
    cudaGetSymbolAddress((void**)&Kh, g_Kh);   cudaGetSymbolAddress((void**)&Kl, g_Kl);
    cudaGetSymbolAddress((void**)&Vth, g_Vth); cudaGetSymbolAddress((void**)&Vtl, g_Vtl);
    cudaGetSymbolAddress((void**)&Chp, g_Ch);  cudaGetSymbolAddress((void**)&Clp, g_Cl);
    cudaGetSymbolAddress((void**)&Ap, g_attn);

    float* attn = ((size_t)out_size >= OUT_ELEMS + ATT_ELEMS) ? (out + OUT_ELEMS) : Ap;

    const int SM128 = 2 * (2 * 128 * 80 + 2 * 128 * 80);  // 81920
    const int SM64  = 2 * (2 * 128 * 80 + 2 * 64 * 80);   // 61440
    const int SMQK  = 2 * (32 * 144) + 2 * (2 * 128 * 144) + 32 * 1028 * 4 + 128; // 214656
    cudaFuncSetAttribute(proj_qk, cudaFuncAttributeMaxDynamicSharedMemorySize, SM128);
    cudaFuncSetAttribute(gemm_pp<128, 0, true>, cudaFuncAttributeMaxDynamicSharedMemorySize, SM128);
    cudaFuncSetAttribute(gemm_pp<64, 3, false>, cudaFuncAttributeMaxDynamicSharedMemorySize, SM64);
    cudaFuncSetAttribute(vproj_qk, cudaFuncAttributeMaxDynamicSharedMemorySize, SMQK);

    // 1) split all inputs to bf16 hi/lo
    split_all<<<16384, 256>>>(query, key, value, Wq, Wk, Wv, Wo);

    dim3 blk(512);

    // 2) Q/K projections (one launch, z = 2)
    proj_qk<<<dim3(8, 32, 2), blk, SM128>>>(
        XQh, XQl, XKh, XKl,
        Wqh, Wql, Wkh, Wkl,
        Qh, Ql, Kh, Kl);

    // 3) FAT kernel: V projection (256 CTAs) co-scheduled with fused
    //    QK^T+softmax (2048 CTAs)
    vproj_qk<<<dim3(256 + 2048), blk, SMQK>>>(
        XVh, XVl, Wvh, Wvl, Vth, Vtl,
        Qh, Ql, Kh, Kl, attn);

    // 4) ctx = attn @ V
    gemm_pp<64, 3, false><<<dim3(1, 8, BB * HH), blk, SM64>>>(
        nullptr, nullptr, attn, Vth, Vtl, nullptr, Chp, Clp,
        SS, SS, SS, 0, (long)SS * SS, (long)DD * SS, 0, 1.0f);

    // 5) out = ctx @ Wo^T
    gemm_pp<128, 0, true><<<dim3(8, 32, 1), blk, SM128>>>(
        Chp, Clp, nullptr, Woh, Wol, out, nullptr, nullptr,
        DMM, DMM, DMM, DMM, 0, 0, 0, 1.0f);
}

// round 16
// speedup vs baseline: 1.0390x; 1.0123x over previous
#include <cuda_runtime.h>
#include <cuda_bf16.h>
#include <cstdint>

#define BB 4
#define SS 1024
#define HH 16
#define DD 64
#define DMM 1024

static const size_t OUT_ELEMS = (size_t)BB * SS * DMM;        // 4194304
static const size_t ATT_ELEMS = (size_t)BB * HH * SS * SS;    // 67108864

#define ACT_N (4096 * 1024)
#define W_N   (1024 * 1024)

// Scratch (__device__ globals) — bf16 hi/lo pairs
__device__ __align__(16) __nv_bfloat16 g_XQh[ACT_N], g_XQl[ACT_N];
__device__ __align__(16) __nv_bfloat16 g_XKh[ACT_N], g_XKl[ACT_N];
__device__ __align__(16) __nv_bfloat16 g_XVh[ACT_N], g_XVl[ACT_N];
__device__ __align__(16) __nv_bfloat16 g_Wqh[W_N], g_Wql[W_N];
__device__ __align__(16) __nv_bfloat16 g_Wkh[W_N], g_Wkl[W_N];
__device__ __align__(16) __nv_bfloat16 g_Wvh[W_N], g_Wvl[W_N];
__device__ __align__(16) __nv_bfloat16 g_Woh[W_N], g_Wol[W_N];
__device__ __align__(16) __nv_bfloat16 g_Qh[ACT_N], g_Ql[ACT_N];   // [bh][s][d]
__device__ __align__(16) __nv_bfloat16 g_Kh[ACT_N], g_Kl[ACT_N];   // [bh][s][d]
__device__ __align__(16) __nv_bfloat16 g_Vth[ACT_N], g_Vtl[ACT_N]; // [bh][d][s]
__device__ __align__(16) __nv_bfloat16 g_Ch[ACT_N], g_Cl[ACT_N];   // ctx [b*s][dm]
__device__ float g_attn[(size_t)BB * HH * SS * SS];                 // fallback

// ---------------------------------------------------------------------------
__device__ __forceinline__ uint32_t smem_u32(const void* p) {
    uint32_t a;
    asm("{ .reg .u64 t; cvta.to.shared.u64 t, %1; cvt.u32.u64 %0, t; }" : "=r"(a) : "l"(p));
    return a;
}
__device__ __forceinline__ void ldsm4(uint32_t* r, uint32_t addr) {
    asm volatile("ldmatrix.sync.aligned.m8n8.x4.shared.b16 {%0,%1,%2,%3}, [%4];"
        : "=r"(r[0]), "=r"(r[1]), "=r"(r[2]), "=r"(r[3]) : "r"(addr));
}
__device__ __forceinline__ void mma16816(float* d, const uint32_t* a, uint32_t b0, uint32_t b1) {
    asm volatile("mma.sync.aligned.m16n8k16.row.col.f32.bf16.bf16.f32 "
        "{%0,%1,%2,%3}, {%4,%5,%6,%7}, {%8,%9}, {%0,%1,%2,%3};"
        : "+f"(d[0]), "+f"(d[1]), "+f"(d[2]), "+f"(d[3])
        : "r"(a[0]), "r"(a[1]), "r"(a[2]), "r"(a[3]), "r"(b0), "r"(b1));
}
__device__ __forceinline__ void cp16(uint32_t s, const void* g) {
    asm volatile("cp.async.cg.shared.global [%0], [%1], 16;" :: "r"(s), "l"(g));
}
#define CP_COMMIT() asm volatile("cp.async.commit_group;" ::: "memory")
#define CP_WAIT(N)  asm volatile("cp.async.wait_group %0;" :: "n"(N) : "memory")
#define STS64(addr, r0, r1) \
    asm volatile("st.shared.v2.b32 [%0], {%1,%2};" :: "r"(addr), "r"(r0), "r"(r1) : "memory")

__device__ __forceinline__ void cvt_pair(float x, float y, uint32_t& hi, uint32_t& lo) {
    __nv_bfloat16 hx = __float2bfloat16(x), hy = __float2bfloat16(y);
    float rx = x - __bfloat162float(hx), ry = y - __bfloat162float(hy);
    __nv_bfloat16 lx = __float2bfloat16(rx), ly = __float2bfloat16(ry);
    hi = ((uint32_t)__bfloat16_as_ushort(hy) << 16) | __bfloat16_as_ushort(hx);
    lo = ((uint32_t)__bfloat16_as_ushort(ly) << 16) | __bfloat16_as_ushort(lx);
}

// ---------------------------------------------------------------------------
// Split fp32 -> bf16 hi/lo for the Q/K-path inputs only (XQ, XK, Wq, Wk).
// 2.5M float4 = 10240 blocks x 256.
// ---------------------------------------------------------------------------
__global__ void __launch_bounds__(256) split_qk(
    const float* q, const float* k, const float* wq, const float* wk)
{
    long i4 = (long)blockIdx.x * blockDim.x + threadIdx.x;
    const float* src; __nv_bfloat16 *dh, *dl; long rel;
    const long M1 = 1048576, Q4 = 262144;
    if (i4 < M1)            { src = q;  dh = g_XQh; dl = g_XQl; rel = i4; }
    else if (i4 < 2*M1)     { src = k;  dh = g_XKh; dl = g_XKl; rel = i4 - M1; }
    else if (i4 < 2*M1+Q4)  { src = wq; dh = g_Wqh; dl = g_Wql; rel = i4 - 2*M1; }
    else                    { src = wk; dh = g_Wkh; dl = g_Wkl; rel = i4 - 2*M1 - Q4; }
    float4 x = ((const float4*)src)[rel];
    uint32_t h0, l0, h1, l1;
    cvt_pair(x.x, x.y, h0, l0);
    cvt_pair(x.z, x.w, h1, l1);
    ((uint2*)dh)[rel] = make_uint2(h0, h1);
    ((uint2*)dl)[rel] = make_uint2(l0, l1);
}

// ---------------------------------------------------------------------------
// Combined Q/K projection GEMM + tail split CTAs for XV/Wv/Wo.
// blockIdx.x < 512  : proj (id>>8 = which proj, (id>>3)&31 = m, id&7 = n)
// blockIdx.x >= 512 : split 4096 float4 of [XV 1M][Wv 256K][Wo 256K]
// ---------------------------------------------------------------------------
__global__ void __launch_bounds__(512, 2) proj_qk(
    const __nv_bfloat16* __restrict__ XQh, const __nv_bfloat16* __restrict__ XQl,
    const __nv_bfloat16* __restrict__ XKh, const __nv_bfloat16* __restrict__ XKl,
    const __nv_bfloat16* __restrict__ Wqh, const __nv_bfloat16* __restrict__ Wql,
    const __nv_bfloat16* __restrict__ Wkh, const __nv_bfloat16* __restrict__ Wkl,
    __nv_bfloat16* __restrict__ Qh, __nv_bfloat16* __restrict__ Ql,
    __nv_bfloat16* __restrict__ Kh, __nv_bfloat16* __restrict__ Kl,
    const float* __restrict__ vin, const float* __restrict__ wv,
    const float* __restrict__ wo)
{
    extern __shared__ char smem[];
    constexpr int RB  = 80;
    constexpr int ASZ = 128 * RB;
    constexpr int BSZ = 128 * RB;
    constexpr int STG = 2 * ASZ + 2 * BSZ;

    const int tid = threadIdx.x, lane = tid & 31, wid = tid >> 5;

    if (blockIdx.x >= 512) {
        // ---- tail: split XV/Wv/Wo (1.5M float4 over 384 CTAs x 4096) ----
        const long base = (long)(blockIdx.x - 512) * 4096;
#pragma unroll
        for (int t = 0; t < 8; ++t) {
            long j = base + tid + t * 512;
            if (j >= 1572864) break;
            const float* src; __nv_bfloat16 *dh, *dl; long rel;
            if (j < 1048576)      { src = vin; dh = g_XVh; dl = g_XVl; rel = j; }
            else if (j < 1310720) { src = wv;  dh = g_Wvh; dl = g_Wvl; rel = j - 1048576; }
            else                  { src = wo;  dh = g_Woh; dl = g_Wol; rel = j - 1310720; }
            float4 x = ((const float4*)src)[rel];
            uint32_t h0, l0, h1, l1;
            cvt_pair(x.x, x.y, h0, l0);
            cvt_pair(x.z, x.w, h1, l1);
            ((uint2*)dh)[rel] = make_uint2(h0, h1);
            ((uint2*)dl)[rel] = make_uint2(l0, l1);
        }
        return;
    }

    const int id = blockIdx.x;
    const int z = id >> 8;
    const int m0 = ((id >> 3) & 31) * 128, n0 = (id & 7) * 128;

    const __nv_bfloat16* Ah = (z == 0) ? XQh : XKh;
    const __nv_bfloat16* Al = (z == 0) ? XQl : XKl;
    const __nv_bfloat16* Bh = (z == 0) ? Wqh : Wkh;
    const __nv_bfloat16* Bl = (z == 0) ? Wql : Wkl;
    __nv_bfloat16* Ch = (z == 0) ? Qh : Kh;
    __nv_bfloat16* Cl = (z == 0) ? Ql : Kl;

    const uint32_t sb = smem_u32(smem);
    const int wm = (wid & 3) * 32, wn = (wid >> 2) * 32;

    Ah += (long)m0 * DMM;
    Al += (long)m0 * DMM;
    Bh += (long)n0 * DMM;
    Bl += (long)n0 * DMM;

    float acc[2][4][4];
#pragma unroll
    for (int mt = 0; mt < 2; ++mt)
#pragma unroll
        for (int nt = 0; nt < 4; ++nt)
#pragma unroll
            for (int j = 0; j < 4; ++j) acc[mt][nt][j] = 0.f;

    auto CPA = [&](int i, int st) {
        int r = tid >> 2, g = tid & 3;
        uint32_t d = sb + (uint32_t)st * STG + (uint32_t)r * RB + (uint32_t)g * 16;
        cp16(d, Ah + (long)r * DMM + i * 32 + g * 8);
        cp16(d + ASZ, Al + (long)r * DMM + i * 32 + g * 8);
    };
    auto CPB = [&](int i, int st) {
        int r = tid >> 2, g = tid & 3;
        uint32_t d = sb + (uint32_t)st * STG + 2 * ASZ + (uint32_t)r * RB + (uint32_t)g * 16;
        cp16(d, Bh + (long)r * DMM + i * 32 + g * 8);
        cp16(d + BSZ, Bl + (long)r * DMM + i * 32 + g * 8);
    };

    const int NC = DMM / 32;
    CPA(0, 0); CPB(0, 0); CP_COMMIT();

    const int aRowOff = (lane & 7) + ((lane >> 3) & 1) * 8;
    const uint32_t aColOff = (uint32_t)((lane >> 4) * 8);
    const int bRowOff = (lane & 7) + ((lane >> 4) & 1) * 8;
    const uint32_t bColOff = (uint32_t)(((lane >> 3) & 1) * 8);

    for (int i = 0; i < NC; ++i) {
        const int s = i & 1;
        if (i + 1 < NC) { CPA(i + 1, s ^ 1); CPB(i + 1, s ^ 1); CP_COMMIT(); CP_WAIT(1); }
        else            { CP_WAIT(0); }
        __syncthreads();

        const uint32_t aB = sb + (uint32_t)s * STG;
        const uint32_t bB = aB + 2 * ASZ;
#pragma unroll
        for (int ks = 0; ks < 2; ++ks) {
            uint32_t ah[2][4], al[2][4];
            const uint32_t ac = (aColOff + ks * 16) * 2;
#pragma unroll
            for (int mt = 0; mt < 2; ++mt) {
                uint32_t ad = aB + (uint32_t)(wm + mt * 16 + aRowOff) * RB + ac;
                ldsm4(ah[mt], ad);
                ldsm4(al[mt], ad + ASZ);
            }
            uint32_t bh[2][4], bl[2][4];
            const uint32_t bc = (bColOff + ks * 16) * 2;
#pragma unroll
            for (int p = 0; p < 2; ++p) {
                uint32_t bd = bB + (uint32_t)(wn + p * 16 + bRowOff) * RB + bc;
                ldsm4(bh[p], bd);
                ldsm4(bl[p], bd + BSZ);
            }
#pragma unroll
            for (int mt = 0; mt < 2; ++mt)
#pragma unroll
                for (int p = 0; p < 2; ++p) {
                    mma16816(acc[mt][2*p],   ah[mt], bh[p][0], bh[p][1]);
                    mma16816(acc[mt][2*p+1], ah[mt], bh[p][2], bh[p][3]);
                }
#pragma unroll
            for (int mt = 0; mt < 2; ++mt)
#pragma unroll
                for (int p = 0; p < 2; ++p) {
                    mma16816(acc[mt][2*p],   al[mt], bh[p][0], bh[p][1]);
                    mma16816(acc[mt][2*p+1], al[mt], bh[p][2], bh[p][3]);
                }
#pragma unroll
            for (int mt = 0; mt < 2; ++mt)
#pragma unroll
                for (int p = 0; p < 2; ++p) {
                    mma16816(acc[mt][2*p],   ah[mt], bl[p][0], bl[p][1]);
                    mma16816(acc[mt][2*p+1], ah[mt], bl[p][2], bl[p][3]);
                }
        }
        __syncthreads();
    }

#pragma unroll
    for (int mt = 0; mt < 2; ++mt)
#pragma unroll
        for (int nt = 0; nt < 4; ++nt) {
#pragma unroll
            for (int half = 0; half < 2; ++half) {
                int m = m0 + wm + mt * 16 + (lane >> 2) + half * 8;
                int n = n0 + wn + nt * 8 + (lane & 3) * 2;
                float x = acc[mt][nt][half * 2], y = acc[mt][nt][half * 2 + 1];
                int h = n >> 6, d = n & 63, b = m >> 10, sI = m & 1023;
                long idx = ((long)(b * HH + h) * SS + sI) * DD + d;
                uint32_t hi, lo;
                cvt_pair(x, y, hi, lo);
                *(uint32_t*)(Ch + idx) = hi;
                *(uint32_t*)(Cl + idx) = lo;
            }
        }
}

// ---------------------------------------------------------------------------
// FAT kernel: blockIdx.x < 256  -> V projection (XV@Wv -> V^T pairs)
//             blockIdx.x >= 256 -> fused QK^T + softmax (R10 proven body)
// ---------------------------------------------------------------------------
__global__ void __launch_bounds__(512) vproj_qk(
    const __nv_bfloat16* __restrict__ XVh, const __nv_bfloat16* __restrict__ XVl,
    const __nv_bfloat16* __restrict__ Wvh, const __nv_bfloat16* __restrict__ Wvl,
    __nv_bfloat16* __restrict__ Vth, __nv_bfloat16* __restrict__ Vtl,
    const __nv_bfloat16* __restrict__ Qh, const __nv_bfloat16* __restrict__ Ql,
    const __nv_bfloat16* __restrict__ Kh, const __nv_bfloat16* __restrict__ Kl,
    float* __restrict__ attn)
{
    extern __shared__ char smem[];
    const uint32_t sb = smem_u32(smem);
    const int tid = threadIdx.x, lane = tid & 31, wid = tid >> 5;

    if (blockIdx.x < 256) {
        constexpr int RB  = 80;
        constexpr int ASZ = 128 * RB;
        constexpr int BSZ = 128 * RB;
        constexpr int STG = 2 * ASZ + 2 * BSZ;

        const int id = blockIdx.x;
        const int m0 = (id >> 3) * 128, n0 = (id & 7) * 128;
        const int wm = (wid & 3) * 32, wn = (wid >> 2) * 32;

        const __nv_bfloat16* Ah = XVh + (long)m0 * DMM;
        const __nv_bfloat16* Al = XVl + (long)m0 * DMM;
        const __nv_bfloat16* Bh = Wvh + (long)n0 * DMM;
        const __nv_bfloat16* Bl = Wvl + (long)n0 * DMM;

        float acc[2][4][4];
#pragma unroll
        for (int mt = 0; mt < 2; ++mt)
#pragma unroll
            for (int nt = 0; nt < 4; ++nt)
#pragma unroll
                for (int j = 0; j < 4; ++j) acc[mt][nt][j] = 0.f;

        auto CPA = [&](int i, int st) {
            int r = tid >> 2, g = tid & 3;
            uint32_t d = sb + (uint32_t)st * STG + (uint32_t)r * RB + (uint32_t)g * 16;
            cp16(d, Ah + (long)r * DMM + i * 32 + g * 8);
            cp16(d + ASZ, Al + (long)r * DMM + i * 32 + g * 8);
        };
        auto CPB = [&](int i, int st) {
            int r = tid >> 2, g = tid & 3;
            uint32_t d = sb + (uint32_t)st * STG + 2 * ASZ + (uint32_t)r * RB + (uint32_t)g * 16;
            cp16(d, Bh + (long)r * DMM + i * 32 + g * 8);
            cp16(d + BSZ, Bl + (long)r * DMM + i * 32 + g * 8);
        };

        const int NC = DMM / 32;
        CPA(0, 0); CPB(0, 0); CP_COMMIT();

        const int aRowOff = (lane & 7) + ((lane >> 3) & 1) * 8;
        const uint32_t aColOff = (uint32_t)((lane >> 4) * 8);
        const int bRowOff = (lane & 7) + ((lane >> 4) & 1) * 8;
        const uint32_t bColOff = (uint32_t)(((lane >> 3) & 1) * 8);

        for (int i = 0; i < NC; ++i) {
            const int s = i & 1;
            if (i + 1 < NC) { CPA(i + 1, s ^ 1); CPB(i + 1, s ^ 1); CP_COMMIT(); CP_WAIT(1); }
            else            { CP_WAIT(0); }
            __syncthreads();

            const uint32_t aB = sb + (uint32_t)s * STG;
            const uint32_t bB = aB + 2 * ASZ;
#pragma unroll
            for (int ks = 0; ks < 2; ++ks) {
                uint32_t ah[2][4], al[2][4];
                const uint32_t ac = (aColOff + ks * 16) * 2;
#pragma unroll
                for (int mt = 0; mt < 2; ++mt) {
                    uint32_t ad = aB + (uint32_t)(wm + mt * 16 + aRowOff) * RB + ac;
                    ldsm4(ah[mt], ad);
                    ldsm4(al[mt], ad + ASZ);
                }
                uint32_t bh[2][4], bl[2][4];
                const uint32_t bc = (bColOff + ks * 16) * 2;
#pragma unroll
                for (int p = 0; p < 2; ++p) {
                    uint32_t bd = bB + (uint32_t)(wn + p * 16 + bRowOff) * RB + bc;
                    ldsm4(bh[p], bd);
                    ldsm4(bl[p], bd + BSZ);
                }
#pragma unroll
                for (int mt = 0; mt < 2; ++mt)
#pragma unroll
                    for (int p = 0; p < 2; ++p) {
                        mma16816(acc[mt][2*p],   ah[mt], bh[p][0], bh[p][1]);
                        mma16816(acc[mt][2*p+1], ah[mt], bh[p][2], bh[p][3]);
                    }
#pragma unroll
                for (int mt = 0; mt < 2; ++mt)
#pragma unroll
                    for (int p = 0; p < 2; ++p) {
                        mma16816(acc[mt][2*p],   al[mt], bh[p][0], bh[p][1]);
                        mma16816(acc[mt][2*p+1], al[mt], bh[p][2], bh[p][3]);
                    }
#pragma unroll
                for (int mt = 0; mt < 2; ++mt)
#pragma unroll
                    for (int p = 0; p < 2; ++p) {
                        mma16816(acc[mt][2*p],   ah[mt], bl[p][0], bl[p][1]);
                        mma16816(acc[mt][2*p+1], ah[mt], bl[p][2], bl[p][3]);
                    }
            }
            __syncthreads();
        }

#pragma unroll
        for (int mt = 0; mt < 2; ++mt)
#pragma unroll
            for (int nt = 0; nt < 4; ++nt) {
#pragma unroll
                for (int half = 0; half < 2; ++half) {
                    int m = m0 + wm + mt * 16 + (lane >> 2) + half * 8;
                    int n = n0 + wn + nt * 8 + (lane & 3) * 2;
                    float x = acc[mt][nt][half * 2], y = acc[mt][nt][half * 2 + 1];
                    int h = n >> 6, d = n & 63, b = m >> 10, sI = m & 1023;
                    long base = ((long)(b * HH + h) * DD + d) * SS + sI;
                    __nv_bfloat16 xh = __float2bfloat16(x);
                    __nv_bfloat16 xl = __float2bfloat16(x - __bfloat162float(xh));
                    __nv_bfloat16 yh = __float2bfloat16(y);
                    __nv_bfloat16 yl = __float2bfloat16(y - __bfloat162float(yh));
                    Vth[base] = xh; Vtl[base] = xl;
                    Vth[base + SS] = yh; Vtl[base + SS] = yl;
                }
            }
        return;
    }

    // ================= fused QK^T + softmax =================
    {
        constexpr int QRB  = 144;
        constexpr int QSZ  = 32 * QRB;
        constexpr int KSZ  = 128 * QRB;
        constexpr int KSTG = 2 * KSZ;
        constexpr int SOFF = 2 * QSZ + 2 * KSTG;
        constexpr int SROW = 1028;

        const uint32_t sQ = sb;
        const uint32_t sK = sb + 2 * QSZ;
        float* Sp = reinterpret_cast<float*>(smem + SOFF);
        float* Ip = reinterpret_cast<float*>(smem + SOFF + 32 * SROW * 4);

        const int id = blockIdx.x - 256;
        const int q0 = (id & 31) * 32;
        const int bh = id >> 5;
        const long qbase = ((long)bh * SS + q0) * DD;
        const long kbase = (long)bh * SS * DD;

        {
            int p = tid >> 8, rem = tid & 255;
            int r = rem >> 3, g = rem & 7;
            const __nv_bfloat16* src = (p ? Ql : Qh) + qbase + (long)r * DD + g * 8;
            cp16(sQ + (uint32_t)p * QSZ + (uint32_t)r * QRB + (uint32_t)g * 16, src);
        }
        auto CPK = [&](int nt, int st) {
#pragma unroll
            for (int j = 0; j < 4; ++j) {
                int idx = tid + j * 512;
                int p = idx >> 10, rem = idx & 1023;
                int r = rem >> 3, g = rem & 7;
                const __nv_bfloat16* src = (p ? Kl : Kh) + kbase + (long)(nt * 128 + r) * DD + g * 8;
                cp16(sK + (uint32_t)st * KSTG + (uint32_t)p * KSZ + (uint32_t)r * QRB + (uint32_t)g * 16, src);
            }
        };
        CPK(0, 0);
        CP_COMMIT();

        const int wm = (wid & 1) * 16, wn = (wid >> 1) * 16;
        const int aRowOff = (lane & 7) + ((lane >> 3) & 1) * 8;
        const uint32_t aColOff = (uint32_t)((lane >> 4) * 8);
        const int bRowOff = (lane & 7) + ((lane >> 4) & 1) * 8;
        const uint32_t bColOff = (uint32_t)(((lane >> 3) & 1) * 8);

        for (int nt = 0; nt < 8; ++nt) {
            const int s = nt & 1;
            if (nt + 1 < 8) { CPK(nt + 1, s ^ 1); CP_COMMIT(); CP_WAIT(1); }
            else            { CP_WAIT(0); }
            __syncthreads();

            float acc[2][4];
#pragma unroll
            for (int j = 0; j < 2; ++j)
#pragma unroll
                for (int v = 0; v < 4; ++v) acc[j][v] = 0.f;

            const uint32_t kB = sK + (uint32_t)s * KSTG;
#pragma unroll
            for (int ks = 0; ks < 4; ++ks) {
                uint32_t ah[4], al[4];
                const uint32_t ac = (aColOff + ks * 16) * 2;
                uint32_t ad = sQ + (uint32_t)(wm + aRowOff) * QRB + ac;
                ldsm4(ah, ad);
                ldsm4(al, ad + QSZ);
                uint32_t bhf[4], blf[4];
                const uint32_t bc = (bColOff + ks * 16) * 2;
                uint32_t bd = kB + (uint32_t)(wn + bRowOff) * QRB + bc;
                ldsm4(bhf, bd);
                ldsm4(blf, bd + KSZ);
                mma16816(acc[0], ah, bhf[0], bhf[1]);
                mma16816(acc[1], ah, bhf[2], bhf[3]);
                mma16816(acc[0], al, bhf[0], bhf[1]);
                mma16816(acc[1], al, bhf[2], bhf[3]);
                mma16816(acc[0], ah, blf[0], blf[1]);
                mma16816(acc[1], ah, blf[2], blf[3]);
            }

            const int m = wm + (lane >> 2);
#pragma unroll
            for (int j = 0; j < 2; ++j) {
                int c = nt * 128 + wn + j * 8 + (lane & 3) * 2;
                float2 e01 = make_float2(__expf(acc[j][0] * 0.125f), __expf(acc[j][1] * 0.125f));
                float2 e23 = make_float2(__expf(acc[j][2] * 0.125f), __expf(acc[j][3] * 0.125f));
                *(float2*)&Sp[(long)m * SROW + c]       = e01;
                *(float2*)&Sp[(long)(m + 8) * SROW + c] = e23;
            }
            __syncthreads();
        }

        {
            int r = tid >> 4, j = tid & 15;
            float sum = 0.f;
#pragma unroll
            for (int k = 0; k < 16; ++k) {
                float4 v = *(float4*)&Sp[(long)r * SROW + j * 4 + k * 64];
                sum += (v.x + v.y) + (v.z + v.w);
            }
            sum += __shfl_xor_sync(0xffffffffu, sum, 1);
            sum += __shfl_xor_sync(0xffffffffu, sum, 2);
            sum += __shfl_xor_sync(0xffffffffu, sum, 4);
            sum += __shfl_xor_sync(0xffffffffu, sum, 8);
            if (j == 0) Ip[r] = 1.0f / sum;
        }
        __syncthreads();

        {
            int r = tid >> 4, j = tid & 15;
            float inv = Ip[r];
            float* dst = attn + ((long)bh * SS + q0 + r) * SS;
#pragma unroll
            for (int k = 0; k < 16; ++k) {
                int c = j * 4 + k * 64;
                float4 v = *(float4*)&Sp[(long)r * SROW + c];
                v.x *= inv; v.y *= inv; v.z *= inv; v.w *= inv;
                *(float4*)&dst[c] = v;
            }
        }
    }
}

// ---------------------------------------------------------------------------
// Split-precision bf16 HMMA GEMM (proven: 512 thr, 2 CTAs/SM, 2-stage).
// MODE: 0 fp32 row-major (*scale); 3 ctx pair out [b*s][dm] (z=bh, n=d)
// PAIRA=false: A fp32 split in-loader.
// ---------------------------------------------------------------------------
template<int NT, int MODE, bool PAIRA>
__global__ void __launch_bounds__(512, 2) gemm_pp(
    const __nv_bfloat16* __restrict__ Ah, const __nv_bfloat16* __restrict__ Al,
    const float* __restrict__ Af,
    const __nv_bfloat16* __restrict__ Bh, const __nv_bfloat16* __restrict__ Bl,
    float* __restrict__ Cf, __nv_bfloat16* __restrict__ Ch, __nv_bfloat16* __restrict__ Cl,
    int K, int lda, int ldb, int ldc,
    long sAz, long sBz, long sCz, float scale)
{
    extern __shared__ char smem[];
    constexpr int RB  = 80;
    constexpr int ASZ = 128 * RB;
    constexpr int BSZ = NT * RB;
    constexpr int STG = 2 * ASZ + 2 * BSZ;
    constexpr int NTP = (NT == 128) ? 2 : 1;
    constexpr int WNE = (NT == 128) ? 32 : 16;

    const uint32_t sb = smem_u32(smem);
    const int tid = threadIdx.x, lane = tid & 31, wid = tid >> 5;
    const int wm = (wid & 3) * 32, wn = (wid >> 2) * WNE;
    const int m0 = blockIdx.y * 128, n0 = blockIdx.x * NT;

    if (PAIRA) {
        Ah += (long)blockIdx.z * sAz + (long)m0 * lda;
        Al += (long)blockIdx.z * sAz + (long)m0 * lda;
    } else {
        Af += (long)blockIdx.z * sAz + (long)m0 * lda;
    }
    Bh += (long)blockIdx.z * sBz + (long)n0 * ldb;
    Bl += (long)blockIdx.z * sBz + (long)n0 * ldb;

    float acc[2][2 * NTP][4];
#pragma unroll
    for (int mt = 0; mt < 2; ++mt)
#pragma unroll
        for (int nt = 0; nt < 2 * NTP; ++nt)
#pragma unroll
            for (int j = 0; j < 4; ++j) acc[mt][nt][j] = 0.f;

    float4 ra[2];

    auto CPA = [&](int i, int st) {
        int r = tid >> 2, g = tid & 3;
        uint32_t d = sb + (uint32_t)st * STG + (uint32_t)r * RB + (uint32_t)g * 16;
        cp16(d, Ah + (long)r * lda + i * 32 + g * 8);
        cp16(d + ASZ, Al + (long)r * lda + i * 32 + g * 8);
    };
    auto CPB = [&](int i, int st) {
        if (NT == 128 || tid < 256) {
            int r = tid >> 2, g = tid & 3;
            uint32_t d = sb + (uint32_t)st * STG + 2 * ASZ + (uint32_t)r * RB + (uint32_t)g * 16;
            cp16(d, Bh + (long)r * ldb + i * 32 + g * 8);
            cp16(d + BSZ, Bl + (long)r * ldb + i * 32 + g * 8);
        }
    };
    auto LDGA = [&](int i) {
#pragma unroll
        for (int t = 0; t < 2; ++t) {
            int c = tid + t * 512, r = c >> 3, g = c & 7;
            ra[t] = *(const float4*)(Af + (long)r * lda + i * 32 + g * 4);
        }
    };
    auto STSA = [&](int st) {
#pragma unroll
        for (int t = 0; t < 2; ++t) {
            int c = tid + t * 512, r = c >> 3, g = c & 7;
            uint32_t h0, l0, h1, l1;
            cvt_pair(ra[t].x, ra[t].y, h0, l0);
            cvt_pair(ra[t].z, ra[t].w, h1, l1);
            uint32_t d = sb + (uint32_t)st * STG + (uint32_t)r * RB + (uint32_t)g * 8;
            STS64(d, h0, h1);
            STS64(d + ASZ, l0, l1);
        }
    };

    const int NC = K / 32;
    if (PAIRA) CPA(0, 0); else LDGA(0);
    CPB(0, 0);
    CP_COMMIT();
    if (!PAIRA) STSA(0);

    const int aRowOff = (lane & 7) + ((lane >> 3) & 1) * 8;
    const uint32_t aColOff = (uint32_t)((lane >> 4) * 8);
    const int bRowOff = (lane & 7) + ((lane >> 4) & 1) * 8;
    const uint32_t bColOff = (uint32_t)(((lane >> 3) & 1) * 8);

    for (int i = 0; i < NC; ++i) {
        const int s = i & 1;
        if (i + 1 < NC) {
            if (PAIRA) CPA(i + 1, s ^ 1);
            else       LDGA(i + 1);
            CPB(i + 1, s ^ 1);
            CP_COMMIT();
            CP_WAIT(1);
        } else {
            CP_WAIT(0);
        }
        __syncthreads();

        const uint32_t aB = sb + (uint32_t)s * STG;
        const uint32_t bB = aB + 2 * ASZ;
#pragma unroll
        for (int ks = 0; ks < 2; ++ks) {
            uint32_t ah[2][4], al[2][4];
            const uint32_t ac = (aColOff + ks * 16) * 2;
#pragma unroll
            for (int mt = 0; mt < 2; ++mt) {
                uint32_t ad = aB + (uint32_t)(wm + mt * 16 + aRowOff) * RB + ac;
                ldsm4(ah[mt], ad);
                ldsm4(al[mt], ad + ASZ);
            }
            uint32_t bh[NTP][4], bl[NTP][4];
            const uint32_t bc = (bColOff + ks * 16) * 2;
#pragma unroll
            for (int p = 0; p < NTP; ++p) {
                uint32_t bd = bB + (uint32_t)(wn + p * 16 + bRowOff) * RB + bc;
                ldsm4(bh[p], bd);
                ldsm4(bl[p], bd + BSZ);
            }
#pragma unroll
            for (int mt = 0; mt < 2; ++mt)
#pragma unroll
                for (int p = 0; p < NTP; ++p) {
                    mma16816(acc[mt][2*p],   ah[mt], bh[p][0], bh[p][1]);
                    mma16816(acc[mt][2*p+1], ah[mt], bh[p][2], bh[p][3]);
                }
#pragma unroll
            for (int mt = 0; mt < 2; ++mt)
#pragma unroll
                for (int p = 0; p < NTP; ++p) {
                    mma16816(acc[mt][2*p],   al[mt], bh[p][0], bh[p][1]);
                    mma16816(acc[mt][2*p+1], al[mt], bh[p][2], bh[p][3]);
                }
#pragma unroll
            for (int mt = 0; mt < 2; ++mt)
#pragma unroll
                for (int p = 0; p < NTP; ++p) {
                    mma16816(acc[mt][2*p],   ah[mt], bl[p][0], bl[p][1]);
                    mma16816(acc[mt][2*p+1], ah[mt], bl[p][2], bl[p][3]);
                }
        }
        if (!PAIRA && i + 1 < NC) STSA(s ^ 1);
        __syncthreads();
    }

    auto emit = [&](int m, int n, float x, float y) {
        if (MODE == 0) {
            float* p = Cf + (long)blockIdx.z * sCz + (long)m * ldc + n;
            *(float2*)p = make_float2(x * scale, y * scale);
        } else {
            int z = blockIdx.z, b = z >> 4, h = z & 15;
            long idx = ((long)(b * SS + m)) * DMM + h * DD + n;
            uint32_t hi, lo;
            cvt_pair(x, y, hi, lo);
            *(uint32_t*)(Ch + idx) = hi;
            *(uint32_t*)(Cl + idx) = lo;
        }
    };

#pragma unroll
    for (int mt = 0; mt < 2; ++mt)
#pragma unroll
        for (int nt = 0; nt < 2 * NTP; ++nt) {
            int m = m0 + wm + mt * 16 + (lane >> 2);
            int n = n0 + wn + nt * 8 + (lane & 3) * 2;
            emit(m,     n, acc[mt][nt][0], acc[mt][nt][1]);
            emit(m + 8, n, acc[mt][nt][2], acc[mt][nt][3]);
        }
}

// ---------------------------------------------------------------------------
extern "C" void kernel_launch(void* const* d_in, const int* in_sizes, int n_in,
                              void* d_out, int out_size)
{
    const float* query = (const float*)d_in[0];
    const float* key   = (const float*)d_in[1];
    const float* value = (const float*)d_in[2];
    const float* Wq    = (const float*)d_in[3];
    const float* Wk    = (const float*)d_in[4];
    const float* Wv    = (const float*)d_in[5];
    const float* Wo    = (const float*)d_in[6];
    float* out = (float*)d_out;

    __nv_bfloat16 *XQh, *XQl, *XKh, *XKl, *XVh, *XVl;
    __nv_bfloat16 *Wqh, *Wql, *Wkh, *Wkl, *Wvh, *Wvl, *Woh, *Wol;
    __nv_bfloat16 *Qh, *Ql, *Kh, *Kl, *Vth, *Vtl, *Chp, *Clp;
    float* Ap;
    cudaGetSymbolAddress((void**)&XQh, g_XQh); cudaGetSymbolAddress((void**)&XQl, g_XQl);
    cudaGetSymbolAddress((void**)&XKh, g_XKh); cudaGetSymbolAddress((void**)&XKl, g_XKl);
    cudaGetSymbolAddress((void**)&XVh, g_XVh); cudaGetSymbolAddress((void**)&XVl, g_XVl);
    cudaGetSymbolAddress((void**)&Wqh, g_Wqh); cudaGetSymbolAddress((void**)&Wql, g_Wql);
    cudaGetSymbolAddress((void**)&Wkh, g_Wkh); cudaGetSymbolAddress((void**)&Wkl, g_Wkl);
    cudaGetSymbolAddress((void**)&Wvh, g_Wvh); cudaGetSymbolAddress((void**)&Wvl, g_Wvl);
    cudaGetSymbolAddress((void**)&Woh, g_Woh); cudaGetSymbolAddress((void**)&Wol, g_Wol);
    cudaGetSymbolAddress((void**)&Qh, g_Qh);   cudaGetSymbolAddress((void**)&Ql, g_Ql);
    cudaGetSymbolAddress((void**)&Kh, g_Kh);   cudaGetSymbolAddress((void**)&Kl, g_Kl);
    cudaGetSymbolAddress((void**)&Vth, g_Vth); cudaGetSymbolAddress((void**)&Vtl, g_Vtl);
    cudaGetSymbolAddress((void**)&Chp, g_Ch);  cudaGetSymbolAddress((void**)&Clp, g_Cl);
    cudaGetSymbolAddress((void**)&Ap, g_attn);

    float* attn = ((size_t)out_size >= OUT_ELEMS + ATT_ELEMS) ? (out + OUT_ELEMS) : Ap;

    const int SM128 = 2 * (2 * 128 * 80 + 2 * 128 * 80);  // 81920
    const int SM64  = 2 * (2 * 128 * 80 + 2 * 64 * 80);   // 61440
    const int SMQK  = 2 * (32 * 144) + 2 * (2 * 128 * 144) + 32 * 1028 * 4 + 128; // 214656
    cudaFuncSetAttribute(proj_qk, cudaFuncAttributeMaxDynamicSharedMemorySize, SM128);
    cudaFuncSetAttribute(gemm_pp<128, 0, true>, cudaFuncAttributeMaxDynamicSharedMemorySize, SM128);
    cudaFuncSetAttribute(gemm_pp<64, 3, false>, cudaFuncAttributeMaxDynamicSharedMemorySize, SM64);
    cudaFuncSetAttribute(vproj_qk, cudaFuncAttributeMaxDynamicSharedMemorySize, SMQK);

    // 1) split the Q/K-path inputs only (2.5M float4)
    split_qk<<<10240, 256>>>(query, key, Wq, Wk);

    dim3 blk(512);

    // 2) Q/K projections + tail CTAs splitting XV/Wv/Wo
    proj_qk<<<dim3(512 + 384), blk, SM128>>>(
        XQh, XQl, XKh, XKl,
        Wqh, Wql, Wkh, Wkl,
        Qh, Ql, Kh, Kl,
        value, Wv, Wo);

    // 3) FAT kernel: V projection (256 CTAs) + fused QK^T+softmax (2048 CTAs)
    vproj_qk<<<dim3(256 + 2048), blk, SMQK>>>(
        XVh, XVl, Wvh, Wvl, Vth, Vtl,
        Qh, Ql, Kh, Kl, attn);

    // 4) ctx = attn @ V
    gemm_pp<64, 3, false><<<dim3(1, 8, BB * HH), blk, SM64>>>(
        nullptr, nullptr, attn, Vth, Vtl, nullptr, Chp, Clp,
        SS, SS, SS, 0, (long)SS * SS, (long)DD * SS, 0, 1.0f);

    // 5) out = ctx @ Wo^T
    gemm_pp<128, 0, true><<<dim3(8, 32, 1), blk, SM128>>>(
        Chp, Clp, nullptr, Woh, Wol, out, nullptr, nullptr,
        DMM, DMM, DMM, DMM, 0, 0, 0, 1.0f);
}